// round 6
// baseline (speedup 1.0000x reference)
#include <cuda_runtime.h>
#include <cuda_bf16.h>
#include <math.h>

#define B_  2
#define S_  2048
#define D_  2048
#define H_  16
#define HD_ 128
#define M_  (B_*S_)          // 4096

#define SCALE_ 0.08838834764831845f   // 1/sqrt(128)

// -------- scratch (allocation-free rule: __device__ globals) --------
static __device__ float g_q [B_*H_*S_*HD_];
static __device__ float g_k [B_*H_*S_*HD_];
static __device__ float g_v [B_*H_*S_*HD_];
static __device__ float g_ao[B_*S_*D_];

// ===================== helpers =========================
__device__ __forceinline__ unsigned smem_u32(const void* p) {
    unsigned a;
    asm("{ .reg .u64 t; cvta.to.shared.u64 t, %1; cvt.u32.u64 %0, t; }"
        : "=r"(a) : "l"(p));
    return a;
}

#define LDSM4(r0,r1,r2,r3,a) \
    asm volatile("ldmatrix.sync.aligned.m8n8.x4.shared.b16 {%0,%1,%2,%3}, [%4];" \
        : "=r"(r0),"=r"(r1),"=r"(r2),"=r"(r3) : "r"(a))

#define MMAT32(d, a0,a1,a2,a3, b0,b1) \
    asm volatile("mma.sync.aligned.m16n8k8.row.col.f32.tf32.tf32.f32 " \
        "{%0,%1,%2,%3}, {%4,%5,%6,%7}, {%8,%9}, {%0,%1,%2,%3};" \
        : "+f"((d)[0]),"+f"((d)[1]),"+f"((d)[2]),"+f"((d)[3]) \
        : "r"(a0),"r"(a1),"r"(a2),"r"(a3),"r"(b0),"r"(b1))

__device__ __forceinline__ float to_tf32(float x) {
    unsigned r;
    asm("cvt.rna.tf32.f32 %0, %1;" : "=r"(r) : "f"(x));
    return __uint_as_float(r);
}
__device__ __forceinline__ unsigned to_tf32u(float x) {
    unsigned r;
    asm("cvt.rna.tf32.f32 %0, %1;" : "=r"(r) : "f"(x));
    return r;
}
__device__ __forceinline__ float4 tf32_4(float4 v) {
    v.x = to_tf32(v.x); v.y = to_tf32(v.y);
    v.z = to_tf32(v.z); v.w = to_tf32(v.w);
    return v;
}

// =====================================================================
// tf32 NT GEMM: C[m,n] = sum_k A[m,k] * W[n,k].
// CTA tile 128x256, warp tile 32x64 (4x4 warp grid), BK=32, 512 threads,
// double-buffered smem, row stride 36 floats (conflict-free ldmatrix).
// scatter=1: z selects Wq/Wk/Wv, writes [B,H,S,HD] into g_q/g_k/g_v
// scatter=0: A := g_ao, W := W0 (Wo), row-major write to Cout
// =====================================================================
#define TM 128
#define TN 256
#define BK2 32
#define GNCH2 (D_/BK2)        // 64
#define GSTR2 36              // floats per row
#define A_SZ (TM*GSTR2*4)     // 18432 bytes
#define B_SZ (TN*GSTR2*4)     // 36864 bytes
#define BUF2 (A_SZ + B_SZ)    // 55296
#define GSMEM2 (2*BUF2)       // 110592

__global__ __launch_bounds__(512, 1) void gemm_tf32(
    const float* __restrict__ A,
    const float* __restrict__ W0, const float* __restrict__ W1,
    const float* __restrict__ W2,
    float* __restrict__ Cout, int scatter)
{
    extern __shared__ char sm_[];
    const unsigned sbase = smem_u32(sm_);

    const int tid = threadIdx.x;
    const int wid = tid >> 5, lid = tid & 31;
    const int m0 = blockIdx.y * TM;
    const int n0 = blockIdx.x * TN;

    const float* W = W0;
    const float* Ap = A;
    float* outq = nullptr;
    if (scatter) {
        if (blockIdx.z == 1)      W = W1;
        else if (blockIdx.z == 2) W = W2;
        outq = (blockIdx.z == 0) ? g_q : (blockIdx.z == 1) ? g_k : g_v;
    } else {
        Ap = g_ao;
    }

    const int wm = wid >> 2, wn = wid & 3;   // warp tile: rows wm*32, cols wn*64

    // ldmatrix lane bases (bytes within region)
    const unsigned aoff0 = (unsigned)(((wm*32 + (lid & 7) + ((lid & 8) ? 8 : 0)) * GSTR2
                                       + ((lid & 16) ? 4 : 0)) * 4);
    const unsigned boff0 = (unsigned)(((wn*64 + (lid & 7) + ((lid & 16) ? 8 : 0)) * GSTR2
                                       + ((lid & 8) ? 4 : 0)) * 4);

    // staging: pos = tid + i*512; row = pos>>3; c4 = (pos&7)*4
    const int srow = tid >> 3, sc4 = (tid & 7) << 2;

    float acc[2][8][4];
#pragma unroll
    for (int mt = 0; mt < 2; mt++)
#pragma unroll
        for (int nt = 0; nt < 8; nt++)
#pragma unroll
            for (int e = 0; e < 4; e++) acc[mt][nt][e] = 0.f;

    float4 pa[2], pb[4];

    // ---- prologue: load + convert chunk 0 into buffer 0 ----
#pragma unroll
    for (int i = 0; i < 2; i++)
        pa[i] = *(const float4*)(Ap + (size_t)(m0 + srow + i*64) * D_ + sc4);
#pragma unroll
    for (int i = 0; i < 4; i++)
        pb[i] = *(const float4*)(W  + (size_t)(n0 + srow + i*64) * D_ + sc4);
    {
        char* st = sm_;
#pragma unroll
        for (int i = 0; i < 2; i++)
            *(float4*)(st + ((srow + i*64)*GSTR2 + sc4)*4) = tf32_4(pa[i]);
#pragma unroll
        for (int i = 0; i < 4; i++)
            *(float4*)(st + A_SZ + ((srow + i*64)*GSTR2 + sc4)*4) = tf32_4(pb[i]);
    }
    __syncthreads();

#pragma unroll 1
    for (int c = 0; c < GNCH2; c++) {
        // prefetch next chunk into registers
        if (c + 1 < GNCH2) {
            int k0 = (c + 1) * BK2;
#pragma unroll
            for (int i = 0; i < 2; i++)
                pa[i] = *(const float4*)(Ap + (size_t)(m0 + srow + i*64) * D_ + k0 + sc4);
#pragma unroll
            for (int i = 0; i < 4; i++)
                pb[i] = *(const float4*)(W  + (size_t)(n0 + srow + i*64) * D_ + k0 + sc4);
        }

        // ---- MMA over current buffer: 4 k8-steps ----
        const unsigned sA = sbase + (unsigned)(c & 1) * BUF2;
        const unsigned sB = sA + A_SZ;
#pragma unroll
        for (int kc = 0; kc < 4; kc++) {
            const unsigned kso = (unsigned)(kc * 32);   // 8 floats
            unsigned a0[2], a1[2], a2[2], a3[2];
#pragma unroll
            for (int mt = 0; mt < 2; mt++)
                LDSM4(a0[mt], a1[mt], a2[mt], a3[mt],
                      sA + aoff0 + (unsigned)(mt*16*GSTR2*4) + kso);
#pragma unroll
            for (int p = 0; p < 4; p++) {
                unsigned b0, b1, b2, b3;
                LDSM4(b0, b1, b2, b3,
                      sB + boff0 + (unsigned)(p*16*GSTR2*4) + kso);
#pragma unroll
                for (int mt = 0; mt < 2; mt++) {
                    MMAT32(acc[mt][2*p],   a0[mt], a1[mt], a2[mt], a3[mt], b0, b1);
                    MMAT32(acc[mt][2*p+1], a0[mt], a1[mt], a2[mt], a3[mt], b2, b3);
                }
            }
        }

        // ---- store prefetched chunk into the other buffer ----
        if (c + 1 < GNCH2) {
            char* st = sm_ + ((c + 1) & 1) * BUF2;
#pragma unroll
            for (int i = 0; i < 2; i++)
                *(float4*)(st + ((srow + i*64)*GSTR2 + sc4)*4) = tf32_4(pa[i]);
#pragma unroll
            for (int i = 0; i < 4; i++)
                *(float4*)(st + A_SZ + ((srow + i*64)*GSTR2 + sc4)*4) = tf32_4(pb[i]);
        }
        __syncthreads();
    }

    // ---- epilogue (c-frag: rows lid>>2 / +8, cols (lid&3)*2) ----
#pragma unroll
    for (int mt = 0; mt < 2; mt++)
#pragma unroll
    for (int nt = 0; nt < 8; nt++) {
        int r  = m0 + wm*32 + mt*16 + (lid >> 2);
        int cc = n0 + wn*64 + nt*8 + (lid & 3)*2;
        if (!scatter) {
            *(float2*)(Cout + (size_t)r * D_ + cc) =
                make_float2(acc[mt][nt][0], acc[mt][nt][1]);
            *(float2*)(Cout + (size_t)(r + 8) * D_ + cc) =
                make_float2(acc[mt][nt][2], acc[mt][nt][3]);
        } else {
            int h = cc >> 7, cd = cc & 127;
            int b1 = r >> 11, s1 = r & (S_ - 1);
            *(float2*)(outq + ((size_t)(b1*H_ + h) * S_ + s1) * HD_ + cd) =
                make_float2(acc[mt][nt][0], acc[mt][nt][1]);
            int r2 = r + 8;
            int b2 = r2 >> 11, s2 = r2 & (S_ - 1);
            *(float2*)(outq + ((size_t)(b2*H_ + h) * S_ + s2) * HD_ + cd) =
                make_float2(acc[mt][nt][2], acc[mt][nt][3]);
        }
    }
}

// =====================================================================
// RoPE in-place on g_q and g_k (float4 vectorized).
// One thread: 4 consecutive d in [0,64) for one (b,h,s).
// =====================================================================
__global__ void rope_kernel(const float* __restrict__ cosT,
                            const float* __restrict__ sinT)
{
    int idx = blockIdx.x * blockDim.x + threadIdx.x;   // over B*H*S*16
    int d4 = (idx & 15) << 2;
    int s  = (idx >> 4) & (S_ - 1);
    int bh = idx >> 15;
    size_t base = ((size_t)bh * S_ + s) * HD_;
    float4 c  = *(const float4*)&cosT[s*HD_ + d4];
    float4 sn = *(const float4*)&sinT[s*HD_ + d4];

    float4 q1 = *(float4*)&g_q[base + d4];
    float4 q2 = *(float4*)&g_q[base + d4 + 64];
    *(float4*)&g_q[base + d4] =
        make_float4(q1.x*c.x - q2.x*sn.x, q1.y*c.y - q2.y*sn.y,
                    q1.z*c.z - q2.z*sn.z, q1.w*c.w - q2.w*sn.w);
    *(float4*)&g_q[base + d4 + 64] =
        make_float4(q2.x*c.x + q1.x*sn.x, q2.y*c.y + q1.y*sn.y,
                    q2.z*c.z + q1.z*sn.z, q2.w*c.w + q1.w*sn.w);

    float4 k1 = *(float4*)&g_k[base + d4];
    float4 k2 = *(float4*)&g_k[base + d4 + 64];
    *(float4*)&g_k[base + d4] =
        make_float4(k1.x*c.x - k2.x*sn.x, k1.y*c.y - k2.y*sn.y,
                    k1.z*c.z - k2.z*sn.z, k1.w*c.w - k2.w*sn.w);
    *(float4*)&g_k[base + d4 + 64] =
        make_float4(k2.x*c.x + k1.x*sn.x, k2.y*c.y + k1.y*sn.y,
                    k2.z*c.z + k1.z*sn.z, k2.w*c.w + k1.w*sn.w);
}

// =====================================================================
// Flash attention on tf32 tensor cores. BQ=128, BK=64, 8 warps.
// (unchanged: 263us)
// =====================================================================
#define QS_STR 132
#define VT_STR 68
#define KS_OFF (128*132)
#define VT_OFF (KS_OFF + 64*132)
#define ATT2_SMEM ((VT_OFF + 128*VT_STR) * 4)   // 136192 bytes

__global__ __launch_bounds__(256, 1) void attn_tc()
{
    extern __shared__ float sm[];
    float* Qs = sm;
    float* Ks = sm + KS_OFF;
    float* VT = sm + VT_OFF;

    const int tid = threadIdx.x;
    const int wid = tid >> 5, lid = tid & 31;
    const int qb  = 15 - (int)blockIdx.x;
    const int bh  = blockIdx.y;
    const int q0  = qb * 128;

    const float* qp = g_q + (size_t)bh * S_ * HD_;
    const float* kp = g_k + (size_t)bh * S_ * HD_;
    const float* vp = g_v + (size_t)bh * S_ * HD_;

#pragma unroll
    for (int i = 0; i < 16; i++) {
        int pos = i*256 + tid;
        int row = pos >> 5;
        int c4  = (pos & 31) << 2;
        float4 v = *(const float4*)&qp[(size_t)(q0 + row) * HD_ + c4];
        *(float4*)&Qs[row*QS_STR + c4] = tf32_4(v);
    }

    const int a_ = lid >> 2, q_ = lid & 3;
    const int r0g = q0 + wid*16 + a_;

    const unsigned aq_base = smem_u32(Qs) +
        (unsigned)(((wid*16 + (lid & 7) + ((lid & 8) ? 8 : 0)) * QS_STR
                    + ((lid & 16) ? 4 : 0)) * 4);
    const unsigned ks_lane = smem_u32(Ks) +
        (unsigned)((((lid & 7) + ((lid & 16) ? 8 : 0)) * QS_STR
                    + ((lid & 8) ? 4 : 0)) * 4);
    const unsigned vt_lane = smem_u32(VT) +
        (unsigned)((((lid & 7) + ((lid & 16) ? 8 : 0)) * VT_STR
                    + ((lid & 8) ? 4 : 0)) * 4);

    float m0 = -INFINITY, m1 = -INFINITY, l0 = 0.f, l1 = 0.f;
    float o[16][4];
#pragma unroll
    for (int f = 0; f < 16; f++)
#pragma unroll
        for (int e = 0; e < 4; e++) o[f][e] = 0.f;

    const int src  = (lid & 0x1C) | (q_ >> 1);
    const int src2 = src + 2;
    const int par  = q_ & 1;

    const int nt = 2*qb + 2;
#pragma unroll 1
    for (int t = 0; t < nt; t++) {
        const int kb = t * 64;
        __syncthreads();
#pragma unroll
        for (int i = 0; i < 8; i++) {
            int pos = i*256 + tid;
            int row = pos >> 5;
            int c4  = (pos & 31) << 2;
            float4 v = *(const float4*)&kp[(size_t)(kb + row) * HD_ + c4];
            *(float4*)&Ks[row*QS_STR + c4] = tf32_4(v);
        }
#pragma unroll
        for (int i = 0; i < 32; i++) {
            int pos = i*256 + tid;
            int key = pos >> 7, hd = pos & 127;
            VT[hd*VT_STR + key] = to_tf32(vp[(size_t)(kb + key) * HD_ + hd]);
        }
        __syncthreads();

        float sc[8][4];
#pragma unroll
        for (int f = 0; f < 8; f++)
#pragma unroll
            for (int e = 0; e < 4; e++) sc[f][e] = 0.f;

#pragma unroll
        for (int kc = 0; kc < 16; kc++) {
            unsigned a0, a1, a2, a3;
            LDSM4(a0, a1, a2, a3, aq_base + (unsigned)(kc*32));
#pragma unroll
            for (int p = 0; p < 4; p++) {
                unsigned b0, b1, b2, b3;
                LDSM4(b0, b1, b2, b3,
                      ks_lane + (unsigned)((p*16*QS_STR + kc*8) * 4));
                MMAT32(sc[2*p],   a0, a1, a2, a3, b0, b1);
                MMAT32(sc[2*p+1], a0, a1, a2, a3, b2, b3);
            }
        }

        const bool maskt = (kb + 63 > q0);
        float mx0 = -INFINITY, mx1 = -INFINITY;
#pragma unroll
        for (int f = 0; f < 8; f++) {
            int cg = kb + f*8 + q_*2;
            float v0 = sc[f][0]*SCALE_, v1 = sc[f][1]*SCALE_;
            float v2 = sc[f][2]*SCALE_, v3 = sc[f][3]*SCALE_;
            if (maskt) {
                if (cg     > r0g)     v0 = -INFINITY;
                if (cg + 1 > r0g)     v1 = -INFINITY;
                if (cg     > r0g + 8) v2 = -INFINITY;
                if (cg + 1 > r0g + 8) v3 = -INFINITY;
            }
            sc[f][0] = v0; sc[f][1] = v1; sc[f][2] = v2; sc[f][3] = v3;
            mx0 = fmaxf(mx0, fmaxf(v0, v1));
            mx1 = fmaxf(mx1, fmaxf(v2, v3));
        }
        mx0 = fmaxf(mx0, __shfl_xor_sync(0xffffffffu, mx0, 1));
        mx0 = fmaxf(mx0, __shfl_xor_sync(0xffffffffu, mx0, 2));
        mx1 = fmaxf(mx1, __shfl_xor_sync(0xffffffffu, mx1, 1));
        mx1 = fmaxf(mx1, __shfl_xor_sync(0xffffffffu, mx1, 2));

        float mn0 = fmaxf(m0, mx0), mn1 = fmaxf(m1, mx1);
        float cr0 = __expf(m0 - mn0), cr1 = __expf(m1 - mn1);
        m0 = mn0; m1 = mn1;
#pragma unroll
        for (int f = 0; f < 16; f++) {
            o[f][0] *= cr0; o[f][1] *= cr0;
            o[f][2] *= cr1; o[f][3] *= cr1;
        }
        float s0 = 0.f, s1 = 0.f;
#pragma unroll
        for (int f = 0; f < 8; f++) {
            float p0 = __expf(sc[f][0] - mn0);
            float p1 = __expf(sc[f][1] - mn0);
            float p2 = __expf(sc[f][2] - mn1);
            float p3 = __expf(sc[f][3] - mn1);
            sc[f][0] = p0; sc[f][1] = p1; sc[f][2] = p2; sc[f][3] = p3;
            s0 += p0 + p1; s1 += p2 + p3;
        }
        l0 = l0*cr0 + s0; l1 = l1*cr1 + s1;

#pragma unroll
        for (int kc8 = 0; kc8 < 8; kc8++) {
            float e0a = __shfl_sync(0xffffffffu, sc[kc8][0], src);
            float e0b = __shfl_sync(0xffffffffu, sc[kc8][1], src);
            float e1a = __shfl_sync(0xffffffffu, sc[kc8][2], src);
            float e1b = __shfl_sync(0xffffffffu, sc[kc8][3], src);
            float e2a = __shfl_sync(0xffffffffu, sc[kc8][0], src2);
            float e2b = __shfl_sync(0xffffffffu, sc[kc8][1], src2);
            float e3a = __shfl_sync(0xffffffffu, sc[kc8][2], src2);
            float e3b = __shfl_sync(0xffffffffu, sc[kc8][3], src2);
            unsigned pa0 = to_tf32u(par ? e0b : e0a);
            unsigned pa1 = to_tf32u(par ? e1b : e1a);
            unsigned pa2 = to_tf32u(par ? e2b : e2a);
            unsigned pa3 = to_tf32u(par ? e3b : e3a);
#pragma unroll
            for (int g = 0; g < 8; g++) {
                unsigned v0, v1, v2, v3;
                LDSM4(v0, v1, v2, v3,
                      vt_lane + (unsigned)((g*16*VT_STR + kc8*8) * 4));
                MMAT32(o[2*g],   pa0, pa1, pa2, pa3, v0, v1);
                MMAT32(o[2*g+1], pa0, pa1, pa2, pa3, v2, v3);
            }
        }
    }

    l0 += __shfl_xor_sync(0xffffffffu, l0, 1);
    l0 += __shfl_xor_sync(0xffffffffu, l0, 2);
    l1 += __shfl_xor_sync(0xffffffffu, l1, 1);
    l1 += __shfl_xor_sync(0xffffffffu, l1, 2);
    float inv0 = 1.f / l0, inv1 = 1.f / l1;

    const int b = bh >> 4, h = bh & 15;
    const int row0 = q0 + wid*16 + a_;
    float* op0 = g_ao + ((size_t)(b*S_ + row0))     * D_ + h*HD_;
    float* op1 = g_ao + ((size_t)(b*S_ + row0 + 8)) * D_ + h*HD_;
#pragma unroll
    for (int f = 0; f < 16; f++) {
        int c = f*8 + q_*2;
        *(float2*)&op0[c] = make_float2(o[f][0]*inv0, o[f][1]*inv0);
        *(float2*)&op1[c] = make_float2(o[f][2]*inv1, o[f][3]*inv1);
    }
}

// =====================================================================
extern "C" void kernel_launch(void* const* d_in, const int* in_sizes, int n_in,
                              void* d_out, int out_size)
{
    (void)in_sizes; (void)n_in; (void)out_size;
    const float* x    = (const float*)d_in[0];
    // d_in[1] = mask: exactly causal, implemented analytically
    const float* cosT = (const float*)d_in[2];
    const float* sinT = (const float*)d_in[3];
    const float* Wq   = (const float*)d_in[4];
    const float* Wk   = (const float*)d_in[5];
    const float* Wv   = (const float*)d_in[6];
    const float* Wo   = (const float*)d_in[7];
    float* out = (float*)d_out;

    cudaFuncSetAttribute(gemm_tf32,
        cudaFuncAttributeMaxDynamicSharedMemorySize, GSMEM2);
    cudaFuncSetAttribute(attn_tc,
        cudaFuncAttributeMaxDynamicSharedMemorySize, ATT2_SMEM);

    // 1) fused QKV projection (tf32 mma) -> [B,H,S,HD]
    dim3 gqkv(D_/TN, M_/TM, 3);
    gemm_tf32<<<gqkv, 512, GSMEM2>>>(x, Wq, Wk, Wv, nullptr, 1);

    // 2) RoPE in place on q,k
    rope_kernel<<<(B_*H_*S_*16)/256, 256>>>(cosT, sinT);

    // 3) causal flash attention (tf32 tensor cores) -> g_ao [B,S,D]
    dim3 gatt(S_/128, B_*H_);
    attn_tc<<<gatt, 256, ATT2_SMEM>>>();

    // 4) output projection (tf32 mma)
    dim3 go(D_/TN, M_/TM, 1);
    gemm_tf32<<<go, 512, GSMEM2>>>(nullptr, Wo, nullptr, nullptr, out, 0);
}

// round 7
// speedup vs baseline: 1.0408x; 1.0408x over previous
#include <cuda_runtime.h>
#include <cuda_bf16.h>
#include <math.h>

#define B_  2
#define S_  2048
#define D_  2048
#define H_  16
#define HD_ 128
#define M_  (B_*S_)          // 4096

#define SCALE_ 0.08838834764831845f   // 1/sqrt(128)

// -------- scratch (allocation-free rule: __device__ globals) --------
static __device__ float g_q [B_*H_*S_*HD_];
static __device__ float g_k [B_*H_*S_*HD_];
static __device__ float g_v [B_*H_*S_*HD_];
static __device__ float g_ao[B_*S_*D_];

// ===================== helpers =========================
__device__ __forceinline__ unsigned smem_u32(const void* p) {
    unsigned a;
    asm("{ .reg .u64 t; cvta.to.shared.u64 t, %1; cvt.u32.u64 %0, t; }"
        : "=r"(a) : "l"(p));
    return a;
}

#define LDSM4(r0,r1,r2,r3,a) \
    asm volatile("ldmatrix.sync.aligned.m8n8.x4.shared.b16 {%0,%1,%2,%3}, [%4];" \
        : "=r"(r0),"=r"(r1),"=r"(r2),"=r"(r3) : "r"(a))

#define MMAT32(d, a0,a1,a2,a3, b0,b1) \
    asm volatile("mma.sync.aligned.m16n8k8.row.col.f32.tf32.tf32.f32 " \
        "{%0,%1,%2,%3}, {%4,%5,%6,%7}, {%8,%9}, {%0,%1,%2,%3};" \
        : "+f"((d)[0]),"+f"((d)[1]),"+f"((d)[2]),"+f"((d)[3]) \
        : "r"(a0),"r"(a1),"r"(a2),"r"(a3),"r"(b0),"r"(b1))

__device__ __forceinline__ float to_tf32(float x) {
    unsigned r;
    asm("cvt.rna.tf32.f32 %0, %1;" : "=r"(r) : "f"(x));
    return __uint_as_float(r);
}
__device__ __forceinline__ unsigned to_tf32u(float x) {
    unsigned r;
    asm("cvt.rna.tf32.f32 %0, %1;" : "=r"(r) : "f"(x));
    return r;
}
__device__ __forceinline__ float4 tf32_4(float4 v) {
    v.x = to_tf32(v.x); v.y = to_tf32(v.y);
    v.z = to_tf32(v.z); v.w = to_tf32(v.w);
    return v;
}

// =====================================================================
// tf32 NT GEMM: C[m,n] = sum_k A[m,k] * W[n,k].
// CTA tile 128x64, warp tile 32x32 (4x2 warp grid), BK=32, 256 threads,
// double-buffered smem (55KB) -> 2 CTAs/SM so staging of one CTA
// overlaps MMA of the other.
// scatter=1: z selects Wq/Wk/Wv, writes [B,H,S,HD] into g_q/g_k/g_v
// scatter=0: A := g_ao, W := W0 (Wo), row-major write to Cout
// =====================================================================
#define TM 128
#define TN 64
#define BK2 32
#define GNCH2 (D_/BK2)        // 64
#define GSTR2 36              // floats per row
#define A_SZ (TM*GSTR2*4)     // 18432 bytes
#define B_SZ (TN*GSTR2*4)     // 9216 bytes
#define BUF2 (A_SZ + B_SZ)    // 27648
#define GSMEM2 (2*BUF2)       // 55296

__global__ __launch_bounds__(256, 2) void gemm_tf32(
    const float* __restrict__ A,
    const float* __restrict__ W0, const float* __restrict__ W1,
    const float* __restrict__ W2,
    float* __restrict__ Cout, int scatter)
{
    extern __shared__ char sm_[];
    const unsigned sbase = smem_u32(sm_);

    const int tid = threadIdx.x;
    const int wid = tid >> 5, lid = tid & 31;
    const int m0 = blockIdx.y * TM;
    const int n0 = blockIdx.x * TN;

    const float* W = W0;
    const float* Ap = A;
    float* outq = nullptr;
    if (scatter) {
        if (blockIdx.z == 1)      W = W1;
        else if (blockIdx.z == 2) W = W2;
        outq = (blockIdx.z == 0) ? g_q : (blockIdx.z == 1) ? g_k : g_v;
    } else {
        Ap = g_ao;
    }

    const int wm = wid >> 1, wn = wid & 1;   // warp tile: rows wm*32, cols wn*32

    // ldmatrix lane bases (bytes within region)
    const unsigned aoff0 = (unsigned)(((wm*32 + (lid & 7) + ((lid & 8) ? 8 : 0)) * GSTR2
                                       + ((lid & 16) ? 4 : 0)) * 4);
    const unsigned boff0 = (unsigned)(((wn*32 + (lid & 7) + ((lid & 16) ? 8 : 0)) * GSTR2
                                       + ((lid & 8) ? 4 : 0)) * 4);

    // staging: pos = tid + i*256; row = pos>>3; c4 = (pos&7)*4
    const int srow = tid >> 3, sc4 = (tid & 7) << 2;

    float acc[2][4][4];
#pragma unroll
    for (int mt = 0; mt < 2; mt++)
#pragma unroll
        for (int nt = 0; nt < 4; nt++)
#pragma unroll
            for (int e = 0; e < 4; e++) acc[mt][nt][e] = 0.f;

    float4 pa[4], pb[2];

    // ---- prologue: load + convert chunk 0 into buffer 0 ----
#pragma unroll
    for (int i = 0; i < 4; i++)
        pa[i] = *(const float4*)(Ap + (size_t)(m0 + srow + i*32) * D_ + sc4);
#pragma unroll
    for (int i = 0; i < 2; i++)
        pb[i] = *(const float4*)(W  + (size_t)(n0 + srow + i*32) * D_ + sc4);
    {
        char* st = sm_;
#pragma unroll
        for (int i = 0; i < 4; i++)
            *(float4*)(st + ((srow + i*32)*GSTR2 + sc4)*4) = tf32_4(pa[i]);
#pragma unroll
        for (int i = 0; i < 2; i++)
            *(float4*)(st + A_SZ + ((srow + i*32)*GSTR2 + sc4)*4) = tf32_4(pb[i]);
    }
    __syncthreads();

#pragma unroll 1
    for (int c = 0; c < GNCH2; c++) {
        // prefetch next chunk into registers
        if (c + 1 < GNCH2) {
            int k0 = (c + 1) * BK2;
#pragma unroll
            for (int i = 0; i < 4; i++)
                pa[i] = *(const float4*)(Ap + (size_t)(m0 + srow + i*32) * D_ + k0 + sc4);
#pragma unroll
            for (int i = 0; i < 2; i++)
                pb[i] = *(const float4*)(W  + (size_t)(n0 + srow + i*32) * D_ + k0 + sc4);
        }

        // ---- MMA over current buffer: 4 k8-steps ----
        const unsigned sA = sbase + (unsigned)(c & 1) * BUF2;
        const unsigned sB = sA + A_SZ;
#pragma unroll
        for (int kc = 0; kc < 4; kc++) {
            const unsigned kso = (unsigned)(kc * 32);   // 8 floats
            unsigned a0[2], a1[2], a2[2], a3[2];
#pragma unroll
            for (int mt = 0; mt < 2; mt++)
                LDSM4(a0[mt], a1[mt], a2[mt], a3[mt],
                      sA + aoff0 + (unsigned)(mt*16*GSTR2*4) + kso);
#pragma unroll
            for (int p = 0; p < 2; p++) {
                unsigned b0, b1, b2, b3;
                LDSM4(b0, b1, b2, b3,
                      sB + boff0 + (unsigned)(p*16*GSTR2*4) + kso);
#pragma unroll
                for (int mt = 0; mt < 2; mt++) {
                    MMAT32(acc[mt][2*p],   a0[mt], a1[mt], a2[mt], a3[mt], b0, b1);
                    MMAT32(acc[mt][2*p+1], a0[mt], a1[mt], a2[mt], a3[mt], b2, b3);
                }
            }
        }

        // ---- store prefetched chunk into the other buffer ----
        if (c + 1 < GNCH2) {
            char* st = sm_ + ((c + 1) & 1) * BUF2;
#pragma unroll
            for (int i = 0; i < 4; i++)
                *(float4*)(st + ((srow + i*32)*GSTR2 + sc4)*4) = tf32_4(pa[i]);
#pragma unroll
            for (int i = 0; i < 2; i++)
                *(float4*)(st + A_SZ + ((srow + i*32)*GSTR2 + sc4)*4) = tf32_4(pb[i]);
        }
        __syncthreads();
    }

    // ---- epilogue (c-frag: rows lid>>2 / +8, cols (lid&3)*2) ----
#pragma unroll
    for (int mt = 0; mt < 2; mt++)
#pragma unroll
    for (int nt = 0; nt < 4; nt++) {
        int r  = m0 + wm*32 + mt*16 + (lid >> 2);
        int cc = n0 + wn*32 + nt*8 + (lid & 3)*2;
        if (!scatter) {
            *(float2*)(Cout + (size_t)r * D_ + cc) =
                make_float2(acc[mt][nt][0], acc[mt][nt][1]);
            *(float2*)(Cout + (size_t)(r + 8) * D_ + cc) =
                make_float2(acc[mt][nt][2], acc[mt][nt][3]);
        } else {
            int h = cc >> 7, cd = cc & 127;
            int b1 = r >> 11, s1 = r & (S_ - 1);
            *(float2*)(outq + ((size_t)(b1*H_ + h) * S_ + s1) * HD_ + cd) =
                make_float2(acc[mt][nt][0], acc[mt][nt][1]);
            int r2 = r + 8;
            int b2 = r2 >> 11, s2 = r2 & (S_ - 1);
            *(float2*)(outq + ((size_t)(b2*H_ + h) * S_ + s2) * HD_ + cd) =
                make_float2(acc[mt][nt][2], acc[mt][nt][3]);
        }
    }
}

// =====================================================================
// RoPE in-place on g_q and g_k (float4 vectorized).
// =====================================================================
__global__ void rope_kernel(const float* __restrict__ cosT,
                            const float* __restrict__ sinT)
{
    int idx = blockIdx.x * blockDim.x + threadIdx.x;   // over B*H*S*16
    int d4 = (idx & 15) << 2;
    int s  = (idx >> 4) & (S_ - 1);
    int bh = idx >> 15;
    size_t base = ((size_t)bh * S_ + s) * HD_;
    float4 c  = *(const float4*)&cosT[s*HD_ + d4];
    float4 sn = *(const float4*)&sinT[s*HD_ + d4];

    float4 q1 = *(float4*)&g_q[base + d4];
    float4 q2 = *(float4*)&g_q[base + d4 + 64];
    *(float4*)&g_q[base + d4] =
        make_float4(q1.x*c.x - q2.x*sn.x, q1.y*c.y - q2.y*sn.y,
                    q1.z*c.z - q2.z*sn.z, q1.w*c.w - q2.w*sn.w);
    *(float4*)&g_q[base + d4 + 64] =
        make_float4(q2.x*c.x + q1.x*sn.x, q2.y*c.y + q1.y*sn.y,
                    q2.z*c.z + q1.z*sn.z, q2.w*c.w + q1.w*sn.w);

    float4 k1 = *(float4*)&g_k[base + d4];
    float4 k2 = *(float4*)&g_k[base + d4 + 64];
    *(float4*)&g_k[base + d4] =
        make_float4(k1.x*c.x - k2.x*sn.x, k1.y*c.y - k2.y*sn.y,
                    k1.z*c.z - k2.z*sn.z, k1.w*c.w - k2.w*sn.w);
    *(float4*)&g_k[base + d4 + 64] =
        make_float4(k2.x*c.x + k1.x*sn.x, k2.y*c.y + k1.y*sn.y,
                    k2.z*c.z + k1.z*sn.z, k2.w*c.w + k1.w*sn.w);
}

// =====================================================================
// Flash attention on tf32 tensor cores. BQ=128, BK=64, 8 warps.
// (unchanged: 263us)
// =====================================================================
#define QS_STR 132
#define VT_STR 68
#define KS_OFF (128*132)
#define VT_OFF (KS_OFF + 64*132)
#define ATT2_SMEM ((VT_OFF + 128*VT_STR) * 4)   // 136192 bytes

__global__ __launch_bounds__(256, 1) void attn_tc()
{
    extern __shared__ float sm[];
    float* Qs = sm;
    float* Ks = sm + KS_OFF;
    float* VT = sm + VT_OFF;

    const int tid = threadIdx.x;
    const int wid = tid >> 5, lid = tid & 31;
    const int qb  = 15 - (int)blockIdx.x;
    const int bh  = blockIdx.y;
    const int q0  = qb * 128;

    const float* qp = g_q + (size_t)bh * S_ * HD_;
    const float* kp = g_k + (size_t)bh * S_ * HD_;
    const float* vp = g_v + (size_t)bh * S_ * HD_;

#pragma unroll
    for (int i = 0; i < 16; i++) {
        int pos = i*256 + tid;
        int row = pos >> 5;
        int c4  = (pos & 31) << 2;
        float4 v = *(const float4*)&qp[(size_t)(q0 + row) * HD_ + c4];
        *(float4*)&Qs[row*QS_STR + c4] = tf32_4(v);
    }

    const int a_ = lid >> 2, q_ = lid & 3;
    const int r0g = q0 + wid*16 + a_;

    const unsigned aq_base = smem_u32(Qs) +
        (unsigned)(((wid*16 + (lid & 7) + ((lid & 8) ? 8 : 0)) * QS_STR
                    + ((lid & 16) ? 4 : 0)) * 4);
    const unsigned ks_lane = smem_u32(Ks) +
        (unsigned)((((lid & 7) + ((lid & 16) ? 8 : 0)) * QS_STR
                    + ((lid & 8) ? 4 : 0)) * 4);
    const unsigned vt_lane = smem_u32(VT) +
        (unsigned)((((lid & 7) + ((lid & 16) ? 8 : 0)) * VT_STR
                    + ((lid & 8) ? 4 : 0)) * 4);

    float m0 = -INFINITY, m1 = -INFINITY, l0 = 0.f, l1 = 0.f;
    float o[16][4];
#pragma unroll
    for (int f = 0; f < 16; f++)
#pragma unroll
        for (int e = 0; e < 4; e++) o[f][e] = 0.f;

    const int src  = (lid & 0x1C) | (q_ >> 1);
    const int src2 = src + 2;
    const int par  = q_ & 1;

    const int nt = 2*qb + 2;
#pragma unroll 1
    for (int t = 0; t < nt; t++) {
        const int kb = t * 64;
        __syncthreads();
#pragma unroll
        for (int i = 0; i < 8; i++) {
            int pos = i*256 + tid;
            int row = pos >> 5;
            int c4  = (pos & 31) << 2;
            float4 v = *(const float4*)&kp[(size_t)(kb + row) * HD_ + c4];
            *(float4*)&Ks[row*QS_STR + c4] = tf32_4(v);
        }
#pragma unroll
        for (int i = 0; i < 32; i++) {
            int pos = i*256 + tid;
            int key = pos >> 7, hd = pos & 127;
            VT[hd*VT_STR + key] = to_tf32(vp[(size_t)(kb + key) * HD_ + hd]);
        }
        __syncthreads();

        float sc[8][4];
#pragma unroll
        for (int f = 0; f < 8; f++)
#pragma unroll
            for (int e = 0; e < 4; e++) sc[f][e] = 0.f;

#pragma unroll
        for (int kc = 0; kc < 16; kc++) {
            unsigned a0, a1, a2, a3;
            LDSM4(a0, a1, a2, a3, aq_base + (unsigned)(kc*32));
#pragma unroll
            for (int p = 0; p < 4; p++) {
                unsigned b0, b1, b2, b3;
                LDSM4(b0, b1, b2, b3,
                      ks_lane + (unsigned)((p*16*QS_STR + kc*8) * 4));
                MMAT32(sc[2*p],   a0, a1, a2, a3, b0, b1);
                MMAT32(sc[2*p+1], a0, a1, a2, a3, b2, b3);
            }
        }

        const bool maskt = (kb + 63 > q0);
        float mx0 = -INFINITY, mx1 = -INFINITY;
#pragma unroll
        for (int f = 0; f < 8; f++) {
            int cg = kb + f*8 + q_*2;
            float v0 = sc[f][0]*SCALE_, v1 = sc[f][1]*SCALE_;
            float v2 = sc[f][2]*SCALE_, v3 = sc[f][3]*SCALE_;
            if (maskt) {
                if (cg     > r0g)     v0 = -INFINITY;
                if (cg + 1 > r0g)     v1 = -INFINITY;
                if (cg     > r0g + 8) v2 = -INFINITY;
                if (cg + 1 > r0g + 8) v3 = -INFINITY;
            }
            sc[f][0] = v0; sc[f][1] = v1; sc[f][2] = v2; sc[f][3] = v3;
            mx0 = fmaxf(mx0, fmaxf(v0, v1));
            mx1 = fmaxf(mx1, fmaxf(v2, v3));
        }
        mx0 = fmaxf(mx0, __shfl_xor_sync(0xffffffffu, mx0, 1));
        mx0 = fmaxf(mx0, __shfl_xor_sync(0xffffffffu, mx0, 2));
        mx1 = fmaxf(mx1, __shfl_xor_sync(0xffffffffu, mx1, 1));
        mx1 = fmaxf(mx1, __shfl_xor_sync(0xffffffffu, mx1, 2));

        float mn0 = fmaxf(m0, mx0), mn1 = fmaxf(m1, mx1);
        float cr0 = __expf(m0 - mn0), cr1 = __expf(m1 - mn1);
        m0 = mn0; m1 = mn1;
#pragma unroll
        for (int f = 0; f < 16; f++) {
            o[f][0] *= cr0; o[f][1] *= cr0;
            o[f][2] *= cr1; o[f][3] *= cr1;
        }
        float s0 = 0.f, s1 = 0.f;
#pragma unroll
        for (int f = 0; f < 8; f++) {
            float p0 = __expf(sc[f][0] - mn0);
            float p1 = __expf(sc[f][1] - mn0);
            float p2 = __expf(sc[f][2] - mn1);
            float p3 = __expf(sc[f][3] - mn1);
            sc[f][0] = p0; sc[f][1] = p1; sc[f][2] = p2; sc[f][3] = p3;
            s0 += p0 + p1; s1 += p2 + p3;
        }
        l0 = l0*cr0 + s0; l1 = l1*cr1 + s1;

#pragma unroll
        for (int kc8 = 0; kc8 < 8; kc8++) {
            float e0a = __shfl_sync(0xffffffffu, sc[kc8][0], src);
            float e0b = __shfl_sync(0xffffffffu, sc[kc8][1], src);
            float e1a = __shfl_sync(0xffffffffu, sc[kc8][2], src);
            float e1b = __shfl_sync(0xffffffffu, sc[kc8][3], src);
            float e2a = __shfl_sync(0xffffffffu, sc[kc8][0], src2);
            float e2b = __shfl_sync(0xffffffffu, sc[kc8][1], src2);
            float e3a = __shfl_sync(0xffffffffu, sc[kc8][2], src2);
            float e3b = __shfl_sync(0xffffffffu, sc[kc8][3], src2);
            unsigned pa0 = to_tf32u(par ? e0b : e0a);
            unsigned pa1 = to_tf32u(par ? e1b : e1a);
            unsigned pa2 = to_tf32u(par ? e2b : e2a);
            unsigned pa3 = to_tf32u(par ? e3b : e3a);
#pragma unroll
            for (int g = 0; g < 8; g++) {
                unsigned v0, v1, v2, v3;
                LDSM4(v0, v1, v2, v3,
                      vt_lane + (unsigned)((g*16*VT_STR + kc8*8) * 4));
                MMAT32(o[2*g],   pa0, pa1, pa2, pa3, v0, v1);
                MMAT32(o[2*g+1], pa0, pa1, pa2, pa3, v2, v3);
            }
        }
    }

    l0 += __shfl_xor_sync(0xffffffffu, l0, 1);
    l0 += __shfl_xor_sync(0xffffffffu, l0, 2);
    l1 += __shfl_xor_sync(0xffffffffu, l1, 1);
    l1 += __shfl_xor_sync(0xffffffffu, l1, 2);
    float inv0 = 1.f / l0, inv1 = 1.f / l1;

    const int b = bh >> 4, h = bh & 15;
    const int row0 = q0 + wid*16 + a_;
    float* op0 = g_ao + ((size_t)(b*S_ + row0))     * D_ + h*HD_;
    float* op1 = g_ao + ((size_t)(b*S_ + row0 + 8)) * D_ + h*HD_;
#pragma unroll
    for (int f = 0; f < 16; f++) {
        int c = f*8 + q_*2;
        *(float2*)&op0[c] = make_float2(o[f][0]*inv0, o[f][1]*inv0);
        *(float2*)&op1[c] = make_float2(o[f][2]*inv1, o[f][3]*inv1);
    }
}

// =====================================================================
extern "C" void kernel_launch(void* const* d_in, const int* in_sizes, int n_in,
                              void* d_out, int out_size)
{
    (void)in_sizes; (void)n_in; (void)out_size;
    const float* x    = (const float*)d_in[0];
    // d_in[1] = mask: exactly causal, implemented analytically
    const float* cosT = (const float*)d_in[2];
    const float* sinT = (const float*)d_in[3];
    const float* Wq   = (const float*)d_in[4];
    const float* Wk   = (const float*)d_in[5];
    const float* Wv   = (const float*)d_in[6];
    const float* Wo   = (const float*)d_in[7];
    float* out = (float*)d_out;

    cudaFuncSetAttribute(gemm_tf32,
        cudaFuncAttributeMaxDynamicSharedMemorySize, GSMEM2);
    cudaFuncSetAttribute(attn_tc,
        cudaFuncAttributeMaxDynamicSharedMemorySize, ATT2_SMEM);

    // 1) fused QKV projection (tf32 mma) -> [B,H,S,HD]
    dim3 gqkv(D_/TN, M_/TM, 3);
    gemm_tf32<<<gqkv, 256, GSMEM2>>>(x, Wq, Wk, Wv, nullptr, 1);

    // 2) RoPE in place on q,k
    rope_kernel<<<(B_*H_*S_*16)/256, 256>>>(cosT, sinT);

    // 3) causal flash attention (tf32 tensor cores) -> g_ao [B,S,D]
    dim3 gatt(S_/128, B_*H_);
    attn_tc<<<gatt, 256, ATT2_SMEM>>>();

    // 4) output projection (tf32 mma)
    dim3 go(D_/TN, M_/TM, 1);
    gemm_tf32<<<go, 256, GSMEM2>>>(nullptr, Wo, nullptr, nullptr, out, 0);
}

// round 8
// speedup vs baseline: 1.4380x; 1.3816x over previous
#include <cuda_runtime.h>
#include <cuda_fp16.h>
#include <math.h>

#define B_  2
#define S_  2048
#define D_  2048
#define H_  16
#define HD_ 128
#define M_  (B_*S_)          // 4096

#define SCALE_ 0.08838834764831845f   // 1/sqrt(128)

// -------- scratch (allocation-free rule: __device__ globals) --------
static __device__ float g_q [B_*H_*S_*HD_];
static __device__ float g_k [B_*H_*S_*HD_];
static __device__ float g_v [B_*H_*S_*HD_];
static __device__ float g_ao[B_*S_*D_];

// ===================== helpers =========================
__device__ __forceinline__ unsigned smem_u32(const void* p) {
    unsigned a;
    asm("{ .reg .u64 t; cvta.to.shared.u64 t, %1; cvt.u32.u64 %0, t; }"
        : "=r"(a) : "l"(p));
    return a;
}

#define LDSM4(r0,r1,r2,r3,a) \
    asm volatile("ldmatrix.sync.aligned.m8n8.x4.shared.b16 {%0,%1,%2,%3}, [%4];" \
        : "=r"(r0),"=r"(r1),"=r"(r2),"=r"(r3) : "r"(a))

#define MMAF16(d, a0,a1,a2,a3, b0,b1) \
    asm volatile("mma.sync.aligned.m16n8k16.row.col.f32.f16.f16.f32 " \
        "{%0,%1,%2,%3}, {%4,%5,%6,%7}, {%8,%9}, {%0,%1,%2,%3};" \
        : "+f"((d)[0]),"+f"((d)[1]),"+f"((d)[2]),"+f"((d)[3]) \
        : "r"(a0),"r"(a1),"r"(a2),"r"(a3),"r"(b0),"r"(b1))

// pack two fp32 -> half2 (lo = first arg)
__device__ __forceinline__ unsigned h2pack(float lo, float hi) {
    unsigned r;
    asm("cvt.rn.f16x2.f32 %0, %1, %2;" : "=r"(r) : "f"(hi), "f"(lo));
    return r;
}
// float4 -> 4 halves (uint2)
__device__ __forceinline__ uint2 h4pack(float4 v) {
    uint2 r;
    r.x = h2pack(v.x, v.y);
    r.y = h2pack(v.z, v.w);
    return r;
}

// =====================================================================
// fp16 NT GEMM: C[m,n] = sum_k A[m,k] * W[n,k]. fp32 accumulate.
// CTA tile 128x64, warp tile 32x32 (4x2 warp grid), BK=32, 256 threads,
// double-buffered fp16 smem (30KB) -> 2 CTAs/SM.
// Row stride 40 halves (80B; ldmatrix conflict-free, validated R3).
// scatter=1: z selects Wq/Wk/Wv, writes [B,H,S,HD] into g_q/g_k/g_v
// scatter=0: A := g_ao, W := W0 (Wo), row-major write to Cout
// =====================================================================
#define TM 128
#define TN 64
#define BK2 32
#define GNCH2 (D_/BK2)        // 64
#define HRS 40                // halves per row
#define A_SZ (TM*HRS*2)       // 10240 bytes
#define B_SZ (TN*HRS*2)       // 5120 bytes
#define BUF2 (A_SZ + B_SZ)    // 15360
#define GSMEM2 (2*BUF2)       // 30720

__global__ __launch_bounds__(256, 2) void gemm_fp16(
    const float* __restrict__ A,
    const float* __restrict__ W0, const float* __restrict__ W1,
    const float* __restrict__ W2,
    float* __restrict__ Cout, int scatter)
{
    extern __shared__ char sm_[];
    const unsigned sbase = smem_u32(sm_);

    const int tid = threadIdx.x;
    const int wid = tid >> 5, lid = tid & 31;
    const int m0 = blockIdx.y * TM;
    const int n0 = blockIdx.x * TN;

    const float* W = W0;
    const float* Ap = A;
    float* outq = nullptr;
    if (scatter) {
        if (blockIdx.z == 1)      W = W1;
        else if (blockIdx.z == 2) W = W2;
        outq = (blockIdx.z == 0) ? g_q : (blockIdx.z == 1) ? g_k : g_v;
    } else {
        Ap = g_ao;
    }

    const int wm = wid >> 1, wn = wid & 1;   // warp tile: rows wm*32, cols wn*32

    // ldmatrix lane bases (bytes)
    const unsigned aoff0 = (unsigned)(((wm*32 + (lid & 7) + ((lid & 8) ? 8 : 0)) * HRS
                                       + ((lid & 16) ? 8 : 0)) * 2);
    const unsigned boff0 = (unsigned)(((wn*32 + (lid & 7) + ((lid & 16) ? 8 : 0)) * HRS
                                       + ((lid & 8) ? 8 : 0)) * 2);

    // staging: row = tid>>3 (+i*32), c4 = (tid&7)*4
    const int srow = tid >> 3, sc4 = (tid & 7) << 2;

    float acc[2][4][4];
#pragma unroll
    for (int mt = 0; mt < 2; mt++)
#pragma unroll
        for (int nt = 0; nt < 4; nt++)
#pragma unroll
            for (int e = 0; e < 4; e++) acc[mt][nt][e] = 0.f;

    float4 pa[4], pb[2];

    // ---- prologue: load + convert chunk 0 into buffer 0 ----
#pragma unroll
    for (int i = 0; i < 4; i++)
        pa[i] = *(const float4*)(Ap + (size_t)(m0 + srow + i*32) * D_ + sc4);
#pragma unroll
    for (int i = 0; i < 2; i++)
        pb[i] = *(const float4*)(W  + (size_t)(n0 + srow + i*32) * D_ + sc4);
    {
        char* st = sm_;
#pragma unroll
        for (int i = 0; i < 4; i++)
            *(uint2*)(st + ((srow + i*32)*HRS + sc4)*2) = h4pack(pa[i]);
#pragma unroll
        for (int i = 0; i < 2; i++)
            *(uint2*)(st + A_SZ + ((srow + i*32)*HRS + sc4)*2) = h4pack(pb[i]);
    }
    __syncthreads();

#pragma unroll 1
    for (int c = 0; c < GNCH2; c++) {
        // prefetch next chunk into registers
        if (c + 1 < GNCH2) {
            int k0 = (c + 1) * BK2;
#pragma unroll
            for (int i = 0; i < 4; i++)
                pa[i] = *(const float4*)(Ap + (size_t)(m0 + srow + i*32) * D_ + k0 + sc4);
#pragma unroll
            for (int i = 0; i < 2; i++)
                pb[i] = *(const float4*)(W  + (size_t)(n0 + srow + i*32) * D_ + k0 + sc4);
        }

        // ---- MMA over current buffer: 2 k16-steps ----
        const unsigned sA = sbase + (unsigned)(c & 1) * BUF2;
        const unsigned sB = sA + A_SZ;
#pragma unroll
        for (int ks = 0; ks < 2; ks++) {
            const unsigned kso = (unsigned)(ks * 32);   // 16 halves
            unsigned a0[2], a1[2], a2[2], a3[2];
#pragma unroll
            for (int mt = 0; mt < 2; mt++)
                LDSM4(a0[mt], a1[mt], a2[mt], a3[mt],
                      sA + aoff0 + (unsigned)(mt*16*HRS*2) + kso);
#pragma unroll
            for (int p = 0; p < 2; p++) {
                unsigned b0, b1, b2, b3;
                LDSM4(b0, b1, b2, b3,
                      sB + boff0 + (unsigned)(p*16*HRS*2) + kso);
#pragma unroll
                for (int mt = 0; mt < 2; mt++) {
                    MMAF16(acc[mt][2*p],   a0[mt], a1[mt], a2[mt], a3[mt], b0, b1);
                    MMAF16(acc[mt][2*p+1], a0[mt], a1[mt], a2[mt], a3[mt], b2, b3);
                }
            }
        }

        // ---- store prefetched chunk into the other buffer ----
        if (c + 1 < GNCH2) {
            char* st = sm_ + ((c + 1) & 1) * BUF2;
#pragma unroll
            for (int i = 0; i < 4; i++)
                *(uint2*)(st + ((srow + i*32)*HRS + sc4)*2) = h4pack(pa[i]);
#pragma unroll
            for (int i = 0; i < 2; i++)
                *(uint2*)(st + A_SZ + ((srow + i*32)*HRS + sc4)*2) = h4pack(pb[i]);
        }
        __syncthreads();
    }

    // ---- epilogue (c-frag: rows lid>>2 / +8, cols (lid&3)*2) ----
#pragma unroll
    for (int mt = 0; mt < 2; mt++)
#pragma unroll
    for (int nt = 0; nt < 4; nt++) {
        int r  = m0 + wm*32 + mt*16 + (lid >> 2);
        int cc = n0 + wn*32 + nt*8 + (lid & 3)*2;
        if (!scatter) {
            *(float2*)(Cout + (size_t)r * D_ + cc) =
                make_float2(acc[mt][nt][0], acc[mt][nt][1]);
            *(float2*)(Cout + (size_t)(r + 8) * D_ + cc) =
                make_float2(acc[mt][nt][2], acc[mt][nt][3]);
        } else {
            int h = cc >> 7, cd = cc & 127;
            int b1 = r >> 11, s1 = r & (S_ - 1);
            *(float2*)(outq + ((size_t)(b1*H_ + h) * S_ + s1) * HD_ + cd) =
                make_float2(acc[mt][nt][0], acc[mt][nt][1]);
            int r2 = r + 8;
            int b2 = r2 >> 11, s2 = r2 & (S_ - 1);
            *(float2*)(outq + ((size_t)(b2*H_ + h) * S_ + s2) * HD_ + cd) =
                make_float2(acc[mt][nt][2], acc[mt][nt][3]);
        }
    }
}

// =====================================================================
// RoPE in-place on g_q and g_k (float4 vectorized).
// =====================================================================
__global__ void rope_kernel(const float* __restrict__ cosT,
                            const float* __restrict__ sinT)
{
    int idx = blockIdx.x * blockDim.x + threadIdx.x;   // over B*H*S*16
    int d4 = (idx & 15) << 2;
    int s  = (idx >> 4) & (S_ - 1);
    int bh = idx >> 15;
    size_t base = ((size_t)bh * S_ + s) * HD_;
    float4 c  = *(const float4*)&cosT[s*HD_ + d4];
    float4 sn = *(const float4*)&sinT[s*HD_ + d4];

    float4 q1 = *(float4*)&g_q[base + d4];
    float4 q2 = *(float4*)&g_q[base + d4 + 64];
    *(float4*)&g_q[base + d4] =
        make_float4(q1.x*c.x - q2.x*sn.x, q1.y*c.y - q2.y*sn.y,
                    q1.z*c.z - q2.z*sn.z, q1.w*c.w - q2.w*sn.w);
    *(float4*)&g_q[base + d4 + 64] =
        make_float4(q2.x*c.x + q1.x*sn.x, q2.y*c.y + q1.y*sn.y,
                    q2.z*c.z + q1.z*sn.z, q2.w*c.w + q1.w*sn.w);

    float4 k1 = *(float4*)&g_k[base + d4];
    float4 k2 = *(float4*)&g_k[base + d4 + 64];
    *(float4*)&g_k[base + d4] =
        make_float4(k1.x*c.x - k2.x*sn.x, k1.y*c.y - k2.y*sn.y,
                    k1.z*c.z - k2.z*sn.z, k1.w*c.w - k2.w*sn.w);
    *(float4*)&g_k[base + d4 + 64] =
        make_float4(k2.x*c.x + k1.x*sn.x, k2.y*c.y + k1.y*sn.y,
                    k2.z*c.z + k1.z*sn.z, k2.w*c.w + k1.w*sn.w);
}

// =====================================================================
// Flash attention on fp16 tensor cores (fp32 accum). BQ=128, BK=64,
// 8 warps, each owns 16 q-rows x all 64 keys. P stays in registers:
// fp16 k16 A-fragment layout == score C-fragment layout (no shuffles).
// V staged transposed. Smem fp16: ~71KB.
// =====================================================================
#define QH 136                 // halves per row, Q/K tiles (17x8 -> conflict-free)
#define VH 72                  // halves per row, VT tile (9x8 -> conflict-free)
#define KS_OFFH (128*QH)               // 17408 halves
#define VT_OFFH (KS_OFFH + 64*QH)      // 26112 halves
#define ATT3_SMEM ((VT_OFFH + 128*VH) * 2)   // 70656 bytes

__global__ __launch_bounds__(256, 1) void attn_fp16()
{
    extern __shared__ __half hsm[];
    __half* Qs = hsm;
    __half* Ks = hsm + KS_OFFH;
    __half* VT = hsm + VT_OFFH;

    const int tid = threadIdx.x;
    const int wid = tid >> 5, lid = tid & 31;
    const int qb  = 15 - (int)blockIdx.x;     // big q-blocks first
    const int bh  = blockIdx.y;
    const int q0  = qb * 128;

    const float* qp = g_q + (size_t)bh * S_ * HD_;
    const float* kp = g_k + (size_t)bh * S_ * HD_;
    const float* vp = g_v + (size_t)bh * S_ * HD_;

    // ---- load Q tile (fp32 -> fp16) ----
#pragma unroll
    for (int i = 0; i < 16; i++) {
        int pos = i*256 + tid;            // 4096 float4s
        int row = pos >> 5;
        int c4  = (pos & 31) << 2;
        float4 v = *(const float4*)&qp[(size_t)(q0 + row) * HD_ + c4];
        *(uint2*)((char*)hsm + (row*QH + c4)*2) = h4pack(v);
    }

    const int a_ = lid >> 2, q_ = lid & 3;
    const int r0g = q0 + wid*16 + a_;

    // ldmatrix lane bases (bytes)
    const unsigned aq_base = smem_u32(Qs) +
        (unsigned)(((wid*16 + (lid & 7) + ((lid & 8) ? 8 : 0)) * QH
                    + ((lid & 16) ? 8 : 0)) * 2);
    const unsigned ks_lane = smem_u32(Ks) +
        (unsigned)((((lid & 7) + ((lid & 16) ? 8 : 0)) * QH
                    + ((lid & 8) ? 8 : 0)) * 2);
    const unsigned vt_lane = smem_u32(VT) +
        (unsigned)((((lid & 7) + ((lid & 16) ? 8 : 0)) * VH
                    + ((lid & 8) ? 8 : 0)) * 2);

    float m0 = -INFINITY, m1 = -INFINITY, l0 = 0.f, l1 = 0.f;
    float o[16][4];
#pragma unroll
    for (int f = 0; f < 16; f++)
#pragma unroll
        for (int e = 0; e < 4; e++) o[f][e] = 0.f;

    const int nt = 2*qb + 2;
#pragma unroll 1
    for (int t = 0; t < nt; t++) {
        const int kb = t * 64;
        __syncthreads();
        // ---- stage K (row-major) and V (transposed) as fp16 ----
#pragma unroll
        for (int i = 0; i < 8; i++) {
            int pos = i*256 + tid;        // 2048 float4s
            int row = pos >> 5;
            int c4  = (pos & 31) << 2;
            float4 v = *(const float4*)&kp[(size_t)(kb + row) * HD_ + c4];
            *(uint2*)((char*)Ks + (row*QH + c4)*2) = h4pack(v);
        }
#pragma unroll
        for (int i = 0; i < 32; i++) {
            int pos = i*256 + tid;        // 8192 scalars
            int key = pos >> 7, hd = pos & 127;
            VT[hd*VH + key] = __float2half_rn(vp[(size_t)(kb + key) * HD_ + hd]);
        }
        __syncthreads();

        // ---- QK^T: scores 16 x 64 per warp (8 k16 steps) ----
        float sc[8][4];
#pragma unroll
        for (int f = 0; f < 8; f++)
#pragma unroll
            for (int e = 0; e < 4; e++) sc[f][e] = 0.f;

#pragma unroll
        for (int kc = 0; kc < 8; kc++) {
            unsigned a0, a1, a2, a3;
            LDSM4(a0, a1, a2, a3, aq_base + (unsigned)(kc*32));
#pragma unroll
            for (int p = 0; p < 4; p++) {
                unsigned b0, b1, b2, b3;
                LDSM4(b0, b1, b2, b3,
                      ks_lane + (unsigned)(p*16*QH*2 + kc*32));
                MMAF16(sc[2*p],   a0, a1, a2, a3, b0, b1);
                MMAF16(sc[2*p+1], a0, a1, a2, a3, b2, b3);
            }
        }

        // ---- online softmax (rows r0g, r0g+8) ----
        const bool maskt = (kb + 63 > q0);
        float mx0 = -INFINITY, mx1 = -INFINITY;
#pragma unroll
        for (int f = 0; f < 8; f++) {
            int cg = kb + f*8 + q_*2;
            float v0 = sc[f][0]*SCALE_, v1 = sc[f][1]*SCALE_;
            float v2 = sc[f][2]*SCALE_, v3 = sc[f][3]*SCALE_;
            if (maskt) {
                if (cg     > r0g)     v0 = -INFINITY;
                if (cg + 1 > r0g)     v1 = -INFINITY;
                if (cg     > r0g + 8) v2 = -INFINITY;
                if (cg + 1 > r0g + 8) v3 = -INFINITY;
            }
            sc[f][0] = v0; sc[f][1] = v1; sc[f][2] = v2; sc[f][3] = v3;
            mx0 = fmaxf(mx0, fmaxf(v0, v1));
            mx1 = fmaxf(mx1, fmaxf(v2, v3));
        }
        mx0 = fmaxf(mx0, __shfl_xor_sync(0xffffffffu, mx0, 1));
        mx0 = fmaxf(mx0, __shfl_xor_sync(0xffffffffu, mx0, 2));
        mx1 = fmaxf(mx1, __shfl_xor_sync(0xffffffffu, mx1, 1));
        mx1 = fmaxf(mx1, __shfl_xor_sync(0xffffffffu, mx1, 2));

        float mn0 = fmaxf(m0, mx0), mn1 = fmaxf(m1, mx1);
        float cr0 = __expf(m0 - mn0), cr1 = __expf(m1 - mn1);
        m0 = mn0; m1 = mn1;
#pragma unroll
        for (int f = 0; f < 16; f++) {
            o[f][0] *= cr0; o[f][1] *= cr0;
            o[f][2] *= cr1; o[f][3] *= cr1;
        }
        float s0 = 0.f, s1 = 0.f;
#pragma unroll
        for (int f = 0; f < 8; f++) {
            float p0 = __expf(sc[f][0] - mn0);
            float p1 = __expf(sc[f][1] - mn0);
            float p2 = __expf(sc[f][2] - mn1);
            float p3 = __expf(sc[f][3] - mn1);
            sc[f][0] = p0; sc[f][1] = p1; sc[f][2] = p2; sc[f][3] = p3;
            s0 += p0 + p1; s1 += p2 + p3;
        }
        l0 = l0*cr0 + s0; l1 = l1*cr1 + s1;

        // ---- P @ V: o[16x128] += P[16x64] V[64x128], 4 k16 chunks ----
#pragma unroll
        for (int kc = 0; kc < 4; kc++) {
            // A fragment = own score regs packed as half2 (layout identity)
            unsigned pa0 = h2pack(sc[2*kc][0],   sc[2*kc][1]);
            unsigned pa1 = h2pack(sc[2*kc][2],   sc[2*kc][3]);
            unsigned pa2 = h2pack(sc[2*kc+1][0], sc[2*kc+1][1]);
            unsigned pa3 = h2pack(sc[2*kc+1][2], sc[2*kc+1][3]);
#pragma unroll
            for (int g = 0; g < 8; g++) {
                unsigned v0, v1, v2, v3;
                LDSM4(v0, v1, v2, v3,
                      vt_lane + (unsigned)(g*16*VH*2 + kc*32));
                MMAF16(o[2*g],   pa0, pa1, pa2, pa3, v0, v1);
                MMAF16(o[2*g+1], pa0, pa1, pa2, pa3, v2, v3);
            }
        }
    }

    // ---- normalize & write [B,S,H*HD] ----
    l0 += __shfl_xor_sync(0xffffffffu, l0, 1);
    l0 += __shfl_xor_sync(0xffffffffu, l0, 2);
    l1 += __shfl_xor_sync(0xffffffffu, l1, 1);
    l1 += __shfl_xor_sync(0xffffffffu, l1, 2);
    float inv0 = 1.f / l0, inv1 = 1.f / l1;

    const int b = bh >> 4, h = bh & 15;
    const int row0 = q0 + wid*16 + a_;
    float* op0 = g_ao + ((size_t)(b*S_ + row0))     * D_ + h*HD_;
    float* op1 = g_ao + ((size_t)(b*S_ + row0 + 8)) * D_ + h*HD_;
#pragma unroll
    for (int f = 0; f < 16; f++) {
        int c = f*8 + q_*2;
        *(float2*)&op0[c] = make_float2(o[f][0]*inv0, o[f][1]*inv0);
        *(float2*)&op1[c] = make_float2(o[f][2]*inv1, o[f][3]*inv1);
    }
}

// =====================================================================
extern "C" void kernel_launch(void* const* d_in, const int* in_sizes, int n_in,
                              void* d_out, int out_size)
{
    (void)in_sizes; (void)n_in; (void)out_size;
    const float* x    = (const float*)d_in[0];
    // d_in[1] = mask: exactly causal, implemented analytically
    const float* cosT = (const float*)d_in[2];
    const float* sinT = (const float*)d_in[3];
    const float* Wq   = (const float*)d_in[4];
    const float* Wk   = (const float*)d_in[5];
    const float* Wv   = (const float*)d_in[6];
    const float* Wo   = (const float*)d_in[7];
    float* out = (float*)d_out;

    cudaFuncSetAttribute(gemm_fp16,
        cudaFuncAttributeMaxDynamicSharedMemorySize, GSMEM2);
    cudaFuncSetAttribute(attn_fp16,
        cudaFuncAttributeMaxDynamicSharedMemorySize, ATT3_SMEM);

    // 1) fused QKV projection (fp16 mma, fp32 accum) -> [B,H,S,HD]
    dim3 gqkv(D_/TN, M_/TM, 3);
    gemm_fp16<<<gqkv, 256, GSMEM2>>>(x, Wq, Wk, Wv, nullptr, 1);

    // 2) RoPE in place on q,k
    rope_kernel<<<(B_*H_*S_*16)/256, 256>>>(cosT, sinT);

    // 3) causal flash attention (fp16 tensor cores) -> g_ao [B,S,D]
    dim3 gatt(S_/128, B_*H_);
    attn_fp16<<<gatt, 256, ATT3_SMEM>>>();

    // 4) output projection (fp16 mma)
    dim3 go(D_/TN, M_/TM, 1);
    gemm_fp16<<<go, 256, GSMEM2>>>(nullptr, Wo, nullptr, nullptr, out, 0);
}

// round 11
// speedup vs baseline: 1.5292x; 1.0635x over previous
#include <cuda_runtime.h>
#include <cuda_fp16.h>
#include <math.h>

#define B_  2
#define S_  2048
#define D_  2048
#define H_  16
#define HD_ 128
#define M_  (B_*S_)          // 4096

#define SCALE_ 0.08838834764831845f   // 1/sqrt(128)

// -------- scratch (fp16, 16B-aligned via uint4 backing) --------
static __device__ uint4 g_qh_raw [B_*H_*S_*HD_/8];
static __device__ uint4 g_kh_raw [B_*H_*S_*HD_/8];
static __device__ uint4 g_vh_raw [B_*H_*S_*HD_/8];
static __device__ uint4 g_aoh_raw[B_*S_*D_/8];
static __device__ uint4 g_xh_raw [B_*S_*D_/8];
static __device__ uint4 g_wq_raw [D_*D_/8];
static __device__ uint4 g_wk_raw [D_*D_/8];
static __device__ uint4 g_wv_raw [D_*D_/8];
static __device__ uint4 g_wo_raw [D_*D_/8];
// device-side accessors ONLY (never touch these from host code!)
#define g_qh  ((__half*)g_qh_raw)
#define g_kh  ((__half*)g_kh_raw)
#define g_vh  ((__half*)g_vh_raw)
#define g_aoh ((__half*)g_aoh_raw)
#define g_xh  ((__half*)g_xh_raw)
#define g_wq  ((__half*)g_wq_raw)
#define g_wk  ((__half*)g_wk_raw)
#define g_wv  ((__half*)g_wv_raw)
#define g_wo  ((__half*)g_wo_raw)

// ===================== helpers =========================
__device__ __forceinline__ unsigned smem_u32(const void* p) {
    unsigned a;
    asm("{ .reg .u64 t; cvta.to.shared.u64 t, %1; cvt.u32.u64 %0, t; }"
        : "=r"(a) : "l"(p));
    return a;
}

#define LDSM4(r0,r1,r2,r3,a) \
    asm volatile("ldmatrix.sync.aligned.m8n8.x4.shared.b16 {%0,%1,%2,%3}, [%4];" \
        : "=r"(r0),"=r"(r1),"=r"(r2),"=r"(r3) : "r"(a))

#define MMAF16(d, a0,a1,a2,a3, b0,b1) \
    asm volatile("mma.sync.aligned.m16n8k16.row.col.f32.f16.f16.f32 " \
        "{%0,%1,%2,%3}, {%4,%5,%6,%7}, {%8,%9}, {%0,%1,%2,%3};" \
        : "+f"((d)[0]),"+f"((d)[1]),"+f"((d)[2]),"+f"((d)[3]) \
        : "r"(a0),"r"(a1),"r"(a2),"r"(a3),"r"(b0),"r"(b1))

// pack two fp32 -> half2 (lo = first arg)
__device__ __forceinline__ unsigned h2pack(float lo, float hi) {
    unsigned r;
    asm("cvt.rn.f16x2.f32 %0, %1, %2;" : "=r"(r) : "f"(hi), "f"(lo));
    return r;
}
__device__ __forceinline__ float2 h2unpack(unsigned u) {
    __half2 h = *(__half2*)&u;
    return __half22float2(h);
}

// =====================================================================
// fp32 -> fp16 bulk convert; dst selected DEVICE-SIDE by `which`
// which: 0=x, 1=Wq, 2=Wk, 3=Wv, 4=Wo
// =====================================================================
__global__ void f2h_kernel(const float* __restrict__ src, int which)
{
    __half* dst = (which == 0) ? g_xh :
                  (which == 1) ? g_wq :
                  (which == 2) ? g_wk :
                  (which == 3) ? g_wv : g_wo;
    int i = (blockIdx.x * blockDim.x + threadIdx.x) * 8;
    float4 a = *(const float4*)(src + i);
    float4 b = *(const float4*)(src + i + 4);
    uint4 r;
    r.x = h2pack(a.x, a.y); r.y = h2pack(a.z, a.w);
    r.z = h2pack(b.x, b.y); r.w = h2pack(b.z, b.w);
    *(uint4*)(dst + i) = r;
}

// =====================================================================
// fp16 NT GEMM (fp32 accum): C[m,n] = sum_k A[m,k] * W[n,k].
// R8-validated pipeline (reg prefetch + STS, CTA 128x64, warp 32x32,
// BK=32, 256 thr, 2 CTA/SM), fp16 global inputs selected device-side.
// mode=0 (QKV): A=g_xh, W per blockIdx.z, scatter fp16 [B,H,S,HD]
// mode=1 (out): A=g_aoh, W=g_wo, write fp32 row-major to Cout
// =====================================================================
#define TM 128
#define TN 64
#define BKH 32
#define GNCH (D_/BKH)         // 64
#define HRS 40                // halves per row
#define ASZ (TM*HRS*2)        // 10240 B
#define BSZ (TN*HRS*2)        // 5120 B
#define BUF (ASZ+BSZ)         // 15360
#define GS  (2*BUF)           // 30720

__global__ __launch_bounds__(256, 2) void gemm_h(float* __restrict__ Cout, int mode)
{
    extern __shared__ char sm_[];
    const unsigned sbase = smem_u32(sm_);

    const int tid = threadIdx.x;
    const int wid = tid >> 5, lid = tid & 31;
    const int m0 = blockIdx.y * TM;
    const int n0 = blockIdx.x * TN;

    const __half* A;
    const __half* W;
    __half* outh = nullptr;
    if (mode == 0) {
        A = g_xh;
        W    = (blockIdx.z == 0) ? g_wq : (blockIdx.z == 1) ? g_wk : g_wv;
        outh = (blockIdx.z == 0) ? g_qh : (blockIdx.z == 1) ? g_kh : g_vh;
    } else {
        A = g_aoh;
        W = g_wo;
    }

    const int wm = wid >> 1, wn = wid & 1;   // warp tile rows wm*32, cols wn*32

    const unsigned aoff0 = (unsigned)(((wm*32 + (lid & 7) + ((lid & 8) ? 8 : 0)) * HRS
                                       + ((lid & 16) ? 8 : 0)) * 2);
    const unsigned boff0 = (unsigned)(((wn*32 + (lid & 7) + ((lid & 16) ? 8 : 0)) * HRS
                                       + ((lid & 8) ? 8 : 0)) * 2);

    // staging: row = tid>>3 (+i*32), half-offset sc4 = (tid&7)*4
    const int srow = tid >> 3, sc4 = (tid & 7) << 2;

    float acc[2][4][4];
#pragma unroll
    for (int mt = 0; mt < 2; mt++)
#pragma unroll
        for (int nt = 0; nt < 4; nt++)
#pragma unroll
            for (int e = 0; e < 4; e++) acc[mt][nt][e] = 0.f;

    uint2 pa[4], pb[2];

    // ---- prologue: load chunk 0 into buffer 0 ----
#pragma unroll
    for (int i = 0; i < 4; i++)
        pa[i] = *(const uint2*)(A + (size_t)(m0 + srow + i*32) * D_ + sc4);
#pragma unroll
    for (int i = 0; i < 2; i++)
        pb[i] = *(const uint2*)(W + (size_t)(n0 + srow + i*32) * D_ + sc4);
    {
        char* st = sm_;
#pragma unroll
        for (int i = 0; i < 4; i++)
            *(uint2*)(st + ((srow + i*32)*HRS + sc4)*2) = pa[i];
#pragma unroll
        for (int i = 0; i < 2; i++)
            *(uint2*)(st + ASZ + ((srow + i*32)*HRS + sc4)*2) = pb[i];
    }
    __syncthreads();

#pragma unroll 1
    for (int c = 0; c < GNCH; c++) {
        // prefetch next chunk into registers
        if (c + 1 < GNCH) {
            int k0 = (c + 1) * BKH;
#pragma unroll
            for (int i = 0; i < 4; i++)
                pa[i] = *(const uint2*)(A + (size_t)(m0 + srow + i*32) * D_ + k0 + sc4);
#pragma unroll
            for (int i = 0; i < 2; i++)
                pb[i] = *(const uint2*)(W + (size_t)(n0 + srow + i*32) * D_ + k0 + sc4);
        }

        // ---- MMA over current buffer: 2 k16-steps ----
        const unsigned sA = sbase + (unsigned)(c & 1) * BUF;
        const unsigned sB = sA + ASZ;
#pragma unroll
        for (int ks = 0; ks < 2; ks++) {
            const unsigned kso = (unsigned)(ks * 32);   // 16 halves
            unsigned a0[2], a1[2], a2[2], a3[2];
#pragma unroll
            for (int mt = 0; mt < 2; mt++)
                LDSM4(a0[mt], a1[mt], a2[mt], a3[mt],
                      sA + aoff0 + (unsigned)(mt*16*HRS*2) + kso);
#pragma unroll
            for (int p = 0; p < 2; p++) {
                unsigned b0, b1, b2, b3;
                LDSM4(b0, b1, b2, b3,
                      sB + boff0 + (unsigned)(p*16*HRS*2) + kso);
#pragma unroll
                for (int mt = 0; mt < 2; mt++) {
                    MMAF16(acc[mt][2*p],   a0[mt], a1[mt], a2[mt], a3[mt], b0, b1);
                    MMAF16(acc[mt][2*p+1], a0[mt], a1[mt], a2[mt], a3[mt], b2, b3);
                }
            }
        }

        // ---- store prefetched chunk into the other buffer ----
        if (c + 1 < GNCH) {
            char* st = sm_ + ((c + 1) & 1) * BUF;
#pragma unroll
            for (int i = 0; i < 4; i++)
                *(uint2*)(st + ((srow + i*32)*HRS + sc4)*2) = pa[i];
#pragma unroll
            for (int i = 0; i < 2; i++)
                *(uint2*)(st + ASZ + ((srow + i*32)*HRS + sc4)*2) = pb[i];
        }
        __syncthreads();
    }

    // ---- epilogue (c-frag: rows lid>>2 / +8, cols (lid&3)*2) ----
#pragma unroll
    for (int mt = 0; mt < 2; mt++)
#pragma unroll
    for (int nt = 0; nt < 4; nt++) {
        int r  = m0 + wm*32 + mt*16 + (lid >> 2);
        int cc = n0 + wn*32 + nt*8 + (lid & 3)*2;
        if (mode != 0) {
            *(float2*)(Cout + (size_t)r * D_ + cc) =
                make_float2(acc[mt][nt][0], acc[mt][nt][1]);
            *(float2*)(Cout + (size_t)(r + 8) * D_ + cc) =
                make_float2(acc[mt][nt][2], acc[mt][nt][3]);
        } else {
            int h = cc >> 7, cd = cc & 127;
            int b1 = r >> 11, s1 = r & (S_ - 1);
            *(unsigned*)(outh + ((size_t)(b1*H_ + h) * S_ + s1) * HD_ + cd) =
                h2pack(acc[mt][nt][0], acc[mt][nt][1]);
            int r2 = r + 8;
            int b2 = r2 >> 11, s2 = r2 & (S_ - 1);
            *(unsigned*)(outh + ((size_t)(b2*H_ + h) * S_ + s2) * HD_ + cd) =
                h2pack(acc[mt][nt][2], acc[mt][nt][3]);
        }
    }
}

// =====================================================================
// RoPE in-place on fp16 g_qh, g_kh (compute fp32, 4 d-values / thread).
// =====================================================================
__global__ void rope_h(const float* __restrict__ cosT,
                       const float* __restrict__ sinT)
{
    int idx = blockIdx.x * blockDim.x + threadIdx.x;   // over B*H*S*16
    int d4 = (idx & 15) << 2;
    int s  = (idx >> 4) & (S_ - 1);
    int bh = idx >> 15;
    size_t base = ((size_t)bh * S_ + s) * HD_;
    float4 c  = *(const float4*)&cosT[s*HD_ + d4];
    float4 sn = *(const float4*)&sinT[s*HD_ + d4];

    uint2 q1u = *(uint2*)(g_qh + base + d4);
    uint2 q2u = *(uint2*)(g_qh + base + d4 + 64);
    float2 q1a = h2unpack(q1u.x), q1b = h2unpack(q1u.y);
    float2 q2a = h2unpack(q2u.x), q2b = h2unpack(q2u.y);
    uint2 o1, o2;
    o1.x = h2pack(q1a.x*c.x - q2a.x*sn.x, q1a.y*c.y - q2a.y*sn.y);
    o1.y = h2pack(q1b.x*c.z - q2b.x*sn.z, q1b.y*c.w - q2b.y*sn.w);
    o2.x = h2pack(q2a.x*c.x + q1a.x*sn.x, q2a.y*c.y + q1a.y*sn.y);
    o2.y = h2pack(q2b.x*c.z + q1b.x*sn.z, q2b.y*c.w + q1b.y*sn.w);
    *(uint2*)(g_qh + base + d4)      = o1;
    *(uint2*)(g_qh + base + d4 + 64) = o2;

    uint2 k1u = *(uint2*)(g_kh + base + d4);
    uint2 k2u = *(uint2*)(g_kh + base + d4 + 64);
    float2 k1a = h2unpack(k1u.x), k1b = h2unpack(k1u.y);
    float2 k2a = h2unpack(k2u.x), k2b = h2unpack(k2u.y);
    o1.x = h2pack(k1a.x*c.x - k2a.x*sn.x, k1a.y*c.y - k2a.y*sn.y);
    o1.y = h2pack(k1b.x*c.z - k2b.x*sn.z, k1b.y*c.w - k2b.y*sn.w);
    o2.x = h2pack(k2a.x*c.x + k1a.x*sn.x, k2a.y*c.y + k1a.y*sn.y);
    o2.y = h2pack(k2b.x*c.z + k1b.x*sn.z, k2b.y*c.w + k1b.y*sn.w);
    *(uint2*)(g_kh + base + d4)      = o1;
    *(uint2*)(g_kh + base + d4 + 64) = o2;
}

// =====================================================================
// Flash attention on fp16 tensor cores (fp32 accum). BQ=128, BK=64,
// 8 warps, P in registers (frag layout identity). fp16 in/out.
// =====================================================================
#define QH 136
#define VH 72
#define KS_OFFH (128*QH)
#define VT_OFFH (KS_OFFH + 64*QH)
#define ATT3_SMEM ((VT_OFFH + 128*VH) * 2)   // 70656 bytes

__global__ __launch_bounds__(256, 1) void attn_h()
{
    extern __shared__ __half hsm[];
    __half* Qs = hsm;
    __half* Ks = hsm + KS_OFFH;
    __half* VT = hsm + VT_OFFH;

    const int tid = threadIdx.x;
    const int wid = tid >> 5, lid = tid & 31;
    const int qb  = 15 - (int)blockIdx.x;
    const int bh  = blockIdx.y;
    const int q0  = qb * 128;

    const __half* qph = g_qh + (size_t)bh * S_ * HD_;
    const __half* kph = g_kh + (size_t)bh * S_ * HD_;
    const __half* vph = g_vh + (size_t)bh * S_ * HD_;

    // ---- load Q tile (direct fp16 copy, 16B segs) ----
#pragma unroll
    for (int i = 0; i < 8; i++) {
        int pos = i*256 + tid;            // 2048 segs
        int row = pos >> 4;
        int seg = pos & 15;
        *(uint4*)(Qs + row*QH + seg*8) =
            *(const uint4*)(qph + (size_t)(q0 + row) * HD_ + seg*8);
    }

    const int a_ = lid >> 2, q_ = lid & 3;
    const int r0g = q0 + wid*16 + a_;

    const unsigned aq_base = smem_u32(Qs) +
        (unsigned)(((wid*16 + (lid & 7) + ((lid & 8) ? 8 : 0)) * QH
                    + ((lid & 16) ? 8 : 0)) * 2);
    const unsigned ks_lane = smem_u32(Ks) +
        (unsigned)((((lid & 7) + ((lid & 16) ? 8 : 0)) * QH
                    + ((lid & 8) ? 8 : 0)) * 2);
    const unsigned vt_lane = smem_u32(VT) +
        (unsigned)((((lid & 7) + ((lid & 16) ? 8 : 0)) * VH
                    + ((lid & 8) ? 8 : 0)) * 2);

    float m0 = -INFINITY, m1 = -INFINITY, l0 = 0.f, l1 = 0.f;
    float o[16][4];
#pragma unroll
    for (int f = 0; f < 16; f++)
#pragma unroll
        for (int e = 0; e < 4; e++) o[f][e] = 0.f;

    const int nt = 2*qb + 2;
#pragma unroll 1
    for (int t = 0; t < nt; t++) {
        const int kb = t * 64;
        __syncthreads();
        // ---- stage K (row-major) and V (transposed) ----
#pragma unroll
        for (int i = 0; i < 4; i++) {
            int pos = i*256 + tid;        // 1024 segs
            int row = pos >> 4;
            int seg = pos & 15;
            *(uint4*)(Ks + row*QH + seg*8) =
                *(const uint4*)(kph + (size_t)(kb + row) * HD_ + seg*8);
        }
#pragma unroll
        for (int i = 0; i < 32; i++) {
            int pos = i*256 + tid;        // 8192 scalars
            int key = pos >> 7, hd = pos & 127;
            VT[hd*VH + key] = vph[(size_t)(kb + key) * HD_ + hd];
        }
        __syncthreads();

        // ---- QK^T ----
        float sc[8][4];
#pragma unroll
        for (int f = 0; f < 8; f++)
#pragma unroll
            for (int e = 0; e < 4; e++) sc[f][e] = 0.f;

#pragma unroll
        for (int kc = 0; kc < 8; kc++) {
            unsigned a0, a1, a2, a3;
            LDSM4(a0, a1, a2, a3, aq_base + (unsigned)(kc*32));
#pragma unroll
            for (int p = 0; p < 4; p++) {
                unsigned b0, b1, b2, b3;
                LDSM4(b0, b1, b2, b3,
                      ks_lane + (unsigned)(p*16*QH*2 + kc*32));
                MMAF16(sc[2*p],   a0, a1, a2, a3, b0, b1);
                MMAF16(sc[2*p+1], a0, a1, a2, a3, b2, b3);
            }
        }

        // ---- online softmax ----
        const bool maskt = (kb + 63 > q0);
        float mx0 = -INFINITY, mx1 = -INFINITY;
#pragma unroll
        for (int f = 0; f < 8; f++) {
            int cg = kb + f*8 + q_*2;
            float v0 = sc[f][0]*SCALE_, v1 = sc[f][1]*SCALE_;
            float v2 = sc[f][2]*SCALE_, v3 = sc[f][3]*SCALE_;
            if (maskt) {
                if (cg     > r0g)     v0 = -INFINITY;
                if (cg + 1 > r0g)     v1 = -INFINITY;
                if (cg     > r0g + 8) v2 = -INFINITY;
                if (cg + 1 > r0g + 8) v3 = -INFINITY;
            }
            sc[f][0] = v0; sc[f][1] = v1; sc[f][2] = v2; sc[f][3] = v3;
            mx0 = fmaxf(mx0, fmaxf(v0, v1));
            mx1 = fmaxf(mx1, fmaxf(v2, v3));
        }
        mx0 = fmaxf(mx0, __shfl_xor_sync(0xffffffffu, mx0, 1));
        mx0 = fmaxf(mx0, __shfl_xor_sync(0xffffffffu, mx0, 2));
        mx1 = fmaxf(mx1, __shfl_xor_sync(0xffffffffu, mx1, 1));
        mx1 = fmaxf(mx1, __shfl_xor_sync(0xffffffffu, mx1, 2));

        float mn0 = fmaxf(m0, mx0), mn1 = fmaxf(m1, mx1);
        float cr0 = __expf(m0 - mn0), cr1 = __expf(m1 - mn1);
        m0 = mn0; m1 = mn1;
#pragma unroll
        for (int f = 0; f < 16; f++) {
            o[f][0] *= cr0; o[f][1] *= cr0;
            o[f][2] *= cr1; o[f][3] *= cr1;
        }
        float s0 = 0.f, s1 = 0.f;
#pragma unroll
        for (int f = 0; f < 8; f++) {
            float p0 = __expf(sc[f][0] - mn0);
            float p1 = __expf(sc[f][1] - mn0);
            float p2 = __expf(sc[f][2] - mn1);
            float p3 = __expf(sc[f][3] - mn1);
            sc[f][0] = p0; sc[f][1] = p1; sc[f][2] = p2; sc[f][3] = p3;
            s0 += p0 + p1; s1 += p2 + p3;
        }
        l0 = l0*cr0 + s0; l1 = l1*cr1 + s1;

        // ---- P @ V ----
#pragma unroll
        for (int kc = 0; kc < 4; kc++) {
            unsigned pa0 = h2pack(sc[2*kc][0],   sc[2*kc][1]);
            unsigned pa1 = h2pack(sc[2*kc][2],   sc[2*kc][3]);
            unsigned pa2 = h2pack(sc[2*kc+1][0], sc[2*kc+1][1]);
            unsigned pa3 = h2pack(sc[2*kc+1][2], sc[2*kc+1][3]);
#pragma unroll
            for (int g = 0; g < 8; g++) {
                unsigned v0, v1, v2, v3;
                LDSM4(v0, v1, v2, v3,
                      vt_lane + (unsigned)(g*16*VH*2 + kc*32));
                MMAF16(o[2*g],   pa0, pa1, pa2, pa3, v0, v1);
                MMAF16(o[2*g+1], pa0, pa1, pa2, pa3, v2, v3);
            }
        }
    }

    // ---- normalize & write fp16 [B,S,H*HD] ----
    l0 += __shfl_xor_sync(0xffffffffu, l0, 1);
    l0 += __shfl_xor_sync(0xffffffffu, l0, 2);
    l1 += __shfl_xor_sync(0xffffffffu, l1, 1);
    l1 += __shfl_xor_sync(0xffffffffu, l1, 2);
    float inv0 = 1.f / l0, inv1 = 1.f / l1;

    const int b = bh >> 4, h = bh & 15;
    const int row0 = q0 + wid*16 + a_;
    __half* op0 = g_aoh + ((size_t)(b*S_ + row0))     * D_ + h*HD_;
    __half* op1 = g_aoh + ((size_t)(b*S_ + row0 + 8)) * D_ + h*HD_;
#pragma unroll
    for (int f = 0; f < 16; f++) {
        int c = f*8 + q_*2;
        *(unsigned*)(op0 + c) = h2pack(o[f][0]*inv0, o[f][1]*inv0);
        *(unsigned*)(op1 + c) = h2pack(o[f][2]*inv1, o[f][3]*inv1);
    }
}

// =====================================================================
extern "C" void kernel_launch(void* const* d_in, const int* in_sizes, int n_in,
                              void* d_out, int out_size)
{
    (void)in_sizes; (void)n_in; (void)out_size;
    const float* x    = (const float*)d_in[0];
    // d_in[1] = mask: exactly causal, implemented analytically
    const float* cosT = (const float*)d_in[2];
    const float* sinT = (const float*)d_in[3];
    const float* Wq   = (const float*)d_in[4];
    const float* Wk   = (const float*)d_in[5];
    const float* Wv   = (const float*)d_in[6];
    const float* Wo   = (const float*)d_in[7];
    float* out = (float*)d_out;

    cudaFuncSetAttribute(gemm_h,
        cudaFuncAttributeMaxDynamicSharedMemorySize, GS);
    cudaFuncSetAttribute(attn_h,
        cudaFuncAttributeMaxDynamicSharedMemorySize, ATT3_SMEM);

    // 0) fp32 -> fp16 conversion of inputs (dst chosen device-side)
    f2h_kernel<<<(B_*S_*D_)/2048, 256>>>(x,  0);
    f2h_kernel<<<(D_*D_)/2048, 256>>>(Wq, 1);
    f2h_kernel<<<(D_*D_)/2048, 256>>>(Wk, 2);
    f2h_kernel<<<(D_*D_)/2048, 256>>>(Wv, 3);
    f2h_kernel<<<(D_*D_)/2048, 256>>>(Wo, 4);

    // 1) fused QKV projection -> fp16 [B,H,S,HD]
    dim3 gqkv(D_/TN, M_/TM, 3);
    gemm_h<<<gqkv, 256, GS>>>(nullptr, 0);

    // 2) RoPE in place on q,k (fp16)
    rope_h<<<(B_*H_*S_*16)/256, 256>>>(cosT, sinT);

    // 3) causal flash attention -> fp16 g_aoh [B,S,D]
    dim3 gatt(S_/128, B_*H_);
    attn_h<<<gatt, 256, ATT3_SMEM>>>();

    // 4) output projection -> fp32 d_out
    dim3 go(D_/TN, M_/TM, 1);
    gemm_h<<<go, 256, GS>>>(out, 1);
}

// round 12
// speedup vs baseline: 1.7896x; 1.1703x over previous
#include <cuda_runtime.h>
#include <cuda_fp16.h>
#include <math.h>

#define B_  2
#define S_  2048
#define D_  2048
#define H_  16
#define HD_ 128
#define M_  (B_*S_)          // 4096

#define SCALE_ 0.08838834764831845f   // 1/sqrt(128)

// -------- scratch (fp16, 16B-aligned via uint4 backing) --------
static __device__ uint4 g_qh_raw [B_*H_*S_*HD_/8];
static __device__ uint4 g_kh_raw [B_*H_*S_*HD_/8];
static __device__ uint4 g_vh_raw [B_*H_*S_*HD_/8];
static __device__ uint4 g_aoh_raw[B_*S_*D_/8];
static __device__ uint4 g_xh_raw [B_*S_*D_/8];
static __device__ uint4 g_wq_raw [D_*D_/8];
static __device__ uint4 g_wk_raw [D_*D_/8];
static __device__ uint4 g_wv_raw [D_*D_/8];
static __device__ uint4 g_wo_raw [D_*D_/8];
// device-side accessors ONLY (never touch these from host code!)
#define g_qh  ((__half*)g_qh_raw)
#define g_kh  ((__half*)g_kh_raw)
#define g_vh  ((__half*)g_vh_raw)
#define g_aoh ((__half*)g_aoh_raw)
#define g_xh  ((__half*)g_xh_raw)
#define g_wq  ((__half*)g_wq_raw)
#define g_wk  ((__half*)g_wk_raw)
#define g_wv  ((__half*)g_wv_raw)
#define g_wo  ((__half*)g_wo_raw)

// ===================== helpers =========================
__device__ __forceinline__ unsigned smem_u32(const void* p) {
    unsigned a;
    asm("{ .reg .u64 t; cvta.to.shared.u64 t, %1; cvt.u32.u64 %0, t; }"
        : "=r"(a) : "l"(p));
    return a;
}

#define LDSM4(r0,r1,r2,r3,a) \
    asm volatile("ldmatrix.sync.aligned.m8n8.x4.shared.b16 {%0,%1,%2,%3}, [%4];" \
        : "=r"(r0),"=r"(r1),"=r"(r2),"=r"(r3) : "r"(a))

#define MMAF16(d, a0,a1,a2,a3, b0,b1) \
    asm volatile("mma.sync.aligned.m16n8k16.row.col.f32.f16.f16.f32 " \
        "{%0,%1,%2,%3}, {%4,%5,%6,%7}, {%8,%9}, {%0,%1,%2,%3};" \
        : "+f"((d)[0]),"+f"((d)[1]),"+f"((d)[2]),"+f"((d)[3]) \
        : "r"(a0),"r"(a1),"r"(a2),"r"(a3),"r"(b0),"r"(b1))

// pack two fp32 -> half2 (lo = first arg)
__device__ __forceinline__ unsigned h2pack(float lo, float hi) {
    unsigned r;
    asm("cvt.rn.f16x2.f32 %0, %1, %2;" : "=r"(r) : "f"(hi), "f"(lo));
    return r;
}
__device__ __forceinline__ float2 h2unpack(unsigned u) {
    __half2 h = *(__half2*)&u;
    return __half22float2(h);
}

// =====================================================================
// fp32 -> fp16 bulk convert; dst selected DEVICE-SIDE by `which`
// which: 0=x, 1=Wq, 2=Wk, 3=Wv, 4=Wo
// =====================================================================
__global__ void f2h_kernel(const float* __restrict__ src, int which)
{
    __half* dst = (which == 0) ? g_xh :
                  (which == 1) ? g_wq :
                  (which == 2) ? g_wk :
                  (which == 3) ? g_wv : g_wo;
    int i = (blockIdx.x * blockDim.x + threadIdx.x) * 8;
    float4 a = *(const float4*)(src + i);
    float4 b = *(const float4*)(src + i + 4);
    uint4 r;
    r.x = h2pack(a.x, a.y); r.y = h2pack(a.z, a.w);
    r.z = h2pack(b.x, b.y); r.w = h2pack(b.z, b.w);
    *(uint4*)(dst + i) = r;
}

// =====================================================================
// fp16 NT GEMM (fp32 accum): C[m,n] = sum_k A[m,k] * W[n,k].
// CTA tile 128x128, warp tile 32x64 (4x2 grid), BK=32, 256 threads,
// reg-prefetch + STS staging (R8/R11-validated), double buffer 40KB,
// 2 CTA/SM. fp16 globals selected device-side.
// mode=0 (QKV): A=g_xh, W per blockIdx.z, scatter fp16 [B,H,S,HD]
// mode=1 (out): A=g_aoh, W=g_wo, write fp32 row-major to Cout
// =====================================================================
#define TM 128
#define TN 128
#define BKH 32
#define GNCH (D_/BKH)         // 64
#define HRS 40                // halves per row
#define ASZ (TM*HRS*2)        // 10240 B
#define BSZ (TN*HRS*2)        // 10240 B
#define BUF (ASZ+BSZ)         // 20480
#define GS  (2*BUF)           // 40960

__global__ __launch_bounds__(256, 2) void gemm_h(float* __restrict__ Cout, int mode)
{
    extern __shared__ char sm_[];
    const unsigned sbase = smem_u32(sm_);

    const int tid = threadIdx.x;
    const int wid = tid >> 5, lid = tid & 31;
    const int m0 = blockIdx.y * TM;
    const int n0 = blockIdx.x * TN;

    const __half* A;
    const __half* W;
    __half* outh = nullptr;
    if (mode == 0) {
        A = g_xh;
        W    = (blockIdx.z == 0) ? g_wq : (blockIdx.z == 1) ? g_wk : g_wv;
        outh = (blockIdx.z == 0) ? g_qh : (blockIdx.z == 1) ? g_kh : g_vh;
    } else {
        A = g_aoh;
        W = g_wo;
    }

    const int wm = wid >> 1, wn = wid & 1;   // warp tile rows wm*32, cols wn*64

    const unsigned aoff0 = (unsigned)(((wm*32 + (lid & 7) + ((lid & 8) ? 8 : 0)) * HRS
                                       + ((lid & 16) ? 8 : 0)) * 2);
    const unsigned boff0 = (unsigned)(((wn*64 + (lid & 7) + ((lid & 16) ? 8 : 0)) * HRS
                                       + ((lid & 8) ? 8 : 0)) * 2);

    // staging: row = tid>>3 (+i*32), half-offset sc4 = (tid&7)*4
    const int srow = tid >> 3, sc4 = (tid & 7) << 2;

    float acc[2][8][4];
#pragma unroll
    for (int mt = 0; mt < 2; mt++)
#pragma unroll
        for (int nt = 0; nt < 8; nt++)
#pragma unroll
            for (int e = 0; e < 4; e++) acc[mt][nt][e] = 0.f;

    uint2 pa[4], pb[4];

    // ---- prologue: load chunk 0 into buffer 0 ----
#pragma unroll
    for (int i = 0; i < 4; i++) {
        pa[i] = *(const uint2*)(A + (size_t)(m0 + srow + i*32) * D_ + sc4);
        pb[i] = *(const uint2*)(W + (size_t)(n0 + srow + i*32) * D_ + sc4);
    }
    {
        char* st = sm_;
#pragma unroll
        for (int i = 0; i < 4; i++) {
            *(uint2*)(st + ((srow + i*32)*HRS + sc4)*2) = pa[i];
            *(uint2*)(st + ASZ + ((srow + i*32)*HRS + sc4)*2) = pb[i];
        }
    }
    __syncthreads();

#pragma unroll 1
    for (int c = 0; c < GNCH; c++) {
        // prefetch next chunk into registers
        if (c + 1 < GNCH) {
            int k0 = (c + 1) * BKH;
#pragma unroll
            for (int i = 0; i < 4; i++) {
                pa[i] = *(const uint2*)(A + (size_t)(m0 + srow + i*32) * D_ + k0 + sc4);
                pb[i] = *(const uint2*)(W + (size_t)(n0 + srow + i*32) * D_ + k0 + sc4);
            }
        }

        // ---- MMA over current buffer: 2 k16-steps ----
        const unsigned sA = sbase + (unsigned)(c & 1) * BUF;
        const unsigned sB = sA + ASZ;
#pragma unroll
        for (int ks = 0; ks < 2; ks++) {
            const unsigned kso = (unsigned)(ks * 32);   // 16 halves
            unsigned a0[2], a1[2], a2[2], a3[2];
#pragma unroll
            for (int mt = 0; mt < 2; mt++)
                LDSM4(a0[mt], a1[mt], a2[mt], a3[mt],
                      sA + aoff0 + (unsigned)(mt*16*HRS*2) + kso);
#pragma unroll
            for (int p = 0; p < 4; p++) {
                unsigned b0, b1, b2, b3;
                LDSM4(b0, b1, b2, b3,
                      sB + boff0 + (unsigned)(p*16*HRS*2) + kso);
#pragma unroll
                for (int mt = 0; mt < 2; mt++) {
                    MMAF16(acc[mt][2*p],   a0[mt], a1[mt], a2[mt], a3[mt], b0, b1);
                    MMAF16(acc[mt][2*p+1], a0[mt], a1[mt], a2[mt], a3[mt], b2, b3);
                }
            }
        }

        // ---- store prefetched chunk into the other buffer ----
        if (c + 1 < GNCH) {
            char* st = sm_ + ((c + 1) & 1) * BUF;
#pragma unroll
            for (int i = 0; i < 4; i++) {
                *(uint2*)(st + ((srow + i*32)*HRS + sc4)*2) = pa[i];
                *(uint2*)(st + ASZ + ((srow + i*32)*HRS + sc4)*2) = pb[i];
            }
        }
        __syncthreads();
    }

    // ---- epilogue (c-frag: rows lid>>2 / +8, cols (lid&3)*2) ----
#pragma unroll
    for (int mt = 0; mt < 2; mt++)
#pragma unroll
    for (int nt = 0; nt < 8; nt++) {
        int r  = m0 + wm*32 + mt*16 + (lid >> 2);
        int cc = n0 + wn*64 + nt*8 + (lid & 3)*2;
        if (mode != 0) {
            *(float2*)(Cout + (size_t)r * D_ + cc) =
                make_float2(acc[mt][nt][0], acc[mt][nt][1]);
            *(float2*)(Cout + (size_t)(r + 8) * D_ + cc) =
                make_float2(acc[mt][nt][2], acc[mt][nt][3]);
        } else {
            int h = cc >> 7, cd = cc & 127;
            int b1 = r >> 11, s1 = r & (S_ - 1);
            *(unsigned*)(outh + ((size_t)(b1*H_ + h) * S_ + s1) * HD_ + cd) =
                h2pack(acc[mt][nt][0], acc[mt][nt][1]);
            int r2 = r + 8;
            int b2 = r2 >> 11, s2 = r2 & (S_ - 1);
            *(unsigned*)(outh + ((size_t)(b2*H_ + h) * S_ + s2) * HD_ + cd) =
                h2pack(acc[mt][nt][2], acc[mt][nt][3]);
        }
    }
}

// =====================================================================
// RoPE in-place on fp16 g_qh, g_kh (compute fp32, 4 d-values / thread).
// =====================================================================
__global__ void rope_h(const float* __restrict__ cosT,
                       const float* __restrict__ sinT)
{
    int idx = blockIdx.x * blockDim.x + threadIdx.x;   // over B*H*S*16
    int d4 = (idx & 15) << 2;
    int s  = (idx >> 4) & (S_ - 1);
    int bh = idx >> 15;
    size_t base = ((size_t)bh * S_ + s) * HD_;
    float4 c  = *(const float4*)&cosT[s*HD_ + d4];
    float4 sn = *(const float4*)&sinT[s*HD_ + d4];

    uint2 q1u = *(uint2*)(g_qh + base + d4);
    uint2 q2u = *(uint2*)(g_qh + base + d4 + 64);
    float2 q1a = h2unpack(q1u.x), q1b = h2unpack(q1u.y);
    float2 q2a = h2unpack(q2u.x), q2b = h2unpack(q2u.y);
    uint2 o1, o2;
    o1.x = h2pack(q1a.x*c.x - q2a.x*sn.x, q1a.y*c.y - q2a.y*sn.y);
    o1.y = h2pack(q1b.x*c.z - q2b.x*sn.z, q1b.y*c.w - q2b.y*sn.w);
    o2.x = h2pack(q2a.x*c.x + q1a.x*sn.x, q2a.y*c.y + q1a.y*sn.y);
    o2.y = h2pack(q2b.x*c.z + q1b.x*sn.z, q2b.y*c.w + q1b.y*sn.w);
    *(uint2*)(g_qh + base + d4)      = o1;
    *(uint2*)(g_qh + base + d4 + 64) = o2;

    uint2 k1u = *(uint2*)(g_kh + base + d4);
    uint2 k2u = *(uint2*)(g_kh + base + d4 + 64);
    float2 k1a = h2unpack(k1u.x), k1b = h2unpack(k1u.y);
    float2 k2a = h2unpack(k2u.x), k2b = h2unpack(k2u.y);
    o1.x = h2pack(k1a.x*c.x - k2a.x*sn.x, k1a.y*c.y - k2a.y*sn.y);
    o1.y = h2pack(k1b.x*c.z - k2b.x*sn.z, k1b.y*c.w - k2b.y*sn.w);
    o2.x = h2pack(k2a.x*c.x + k1a.x*sn.x, k2a.y*c.y + k1a.y*sn.y);
    o2.y = h2pack(k2b.x*c.z + k1b.x*sn.z, k2b.y*c.w + k1b.y*sn.w);
    *(uint2*)(g_kh + base + d4)      = o1;
    *(uint2*)(g_kh + base + d4 + 64) = o2;
}

// =====================================================================
// Flash attention on fp16 tensor cores (fp32 accum). BQ=128, BK=64,
// 8 warps, P in registers (frag layout identity). fp16 in/out.
// (unchanged from R11)
// =====================================================================
#define QH 136
#define VH 72
#define KS_OFFH (128*QH)
#define VT_OFFH (KS_OFFH + 64*QH)
#define ATT3_SMEM ((VT_OFFH + 128*VH) * 2)   // 70656 bytes

__global__ __launch_bounds__(256, 1) void attn_h()
{
    extern __shared__ __half hsm[];
    __half* Qs = hsm;
    __half* Ks = hsm + KS_OFFH;
    __half* VT = hsm + VT_OFFH;

    const int tid = threadIdx.x;
    const int wid = tid >> 5, lid = tid & 31;
    const int qb  = 15 - (int)blockIdx.x;
    const int bh  = blockIdx.y;
    const int q0  = qb * 128;

    const __half* qph = g_qh + (size_t)bh * S_ * HD_;
    const __half* kph = g_kh + (size_t)bh * S_ * HD_;
    const __half* vph = g_vh + (size_t)bh * S_ * HD_;

    // ---- load Q tile (direct fp16 copy, 16B segs) ----
#pragma unroll
    for (int i = 0; i < 8; i++) {
        int pos = i*256 + tid;            // 2048 segs
        int row = pos >> 4;
        int seg = pos & 15;
        *(uint4*)(Qs + row*QH + seg*8) =
            *(const uint4*)(qph + (size_t)(q0 + row) * HD_ + seg*8);
    }

    const int a_ = lid >> 2, q_ = lid & 3;
    const int r0g = q0 + wid*16 + a_;

    const unsigned aq_base = smem_u32(Qs) +
        (unsigned)(((wid*16 + (lid & 7) + ((lid & 8) ? 8 : 0)) * QH
                    + ((lid & 16) ? 8 : 0)) * 2);
    const unsigned ks_lane = smem_u32(Ks) +
        (unsigned)((((lid & 7) + ((lid & 16) ? 8 : 0)) * QH
                    + ((lid & 8) ? 8 : 0)) * 2);
    const unsigned vt_lane = smem_u32(VT) +
        (unsigned)((((lid & 7) + ((lid & 16) ? 8 : 0)) * VH
                    + ((lid & 8) ? 8 : 0)) * 2);

    float m0 = -INFINITY, m1 = -INFINITY, l0 = 0.f, l1 = 0.f;
    float o[16][4];
#pragma unroll
    for (int f = 0; f < 16; f++)
#pragma unroll
        for (int e = 0; e < 4; e++) o[f][e] = 0.f;

    const int nt = 2*qb + 2;
#pragma unroll 1
    for (int t = 0; t < nt; t++) {
        const int kb = t * 64;
        __syncthreads();
        // ---- stage K (row-major) and V (transposed) ----
#pragma unroll
        for (int i = 0; i < 4; i++) {
            int pos = i*256 + tid;        // 1024 segs
            int row = pos >> 4;
            int seg = pos & 15;
            *(uint4*)(Ks + row*QH + seg*8) =
                *(const uint4*)(kph + (size_t)(kb + row) * HD_ + seg*8);
        }
#pragma unroll
        for (int i = 0; i < 32; i++) {
            int pos = i*256 + tid;        // 8192 scalars
            int key = pos >> 7, hd = pos & 127;
            VT[hd*VH + key] = vph[(size_t)(kb + key) * HD_ + hd];
        }
        __syncthreads();

        // ---- QK^T ----
        float sc[8][4];
#pragma unroll
        for (int f = 0; f < 8; f++)
#pragma unroll
            for (int e = 0; e < 4; e++) sc[f][e] = 0.f;

#pragma unroll
        for (int kc = 0; kc < 8; kc++) {
            unsigned a0, a1, a2, a3;
            LDSM4(a0, a1, a2, a3, aq_base + (unsigned)(kc*32));
#pragma unroll
            for (int p = 0; p < 4; p++) {
                unsigned b0, b1, b2, b3;
                LDSM4(b0, b1, b2, b3,
                      ks_lane + (unsigned)(p*16*QH*2 + kc*32));
                MMAF16(sc[2*p],   a0, a1, a2, a3, b0, b1);
                MMAF16(sc[2*p+1], a0, a1, a2, a3, b2, b3);
            }
        }

        // ---- online softmax ----
        const bool maskt = (kb + 63 > q0);
        float mx0 = -INFINITY, mx1 = -INFINITY;
#pragma unroll
        for (int f = 0; f < 8; f++) {
            int cg = kb + f*8 + q_*2;
            float v0 = sc[f][0]*SCALE_, v1 = sc[f][1]*SCALE_;
            float v2 = sc[f][2]*SCALE_, v3 = sc[f][3]*SCALE_;
            if (maskt) {
                if (cg     > r0g)     v0 = -INFINITY;
                if (cg + 1 > r0g)     v1 = -INFINITY;
                if (cg     > r0g + 8) v2 = -INFINITY;
                if (cg + 1 > r0g + 8) v3 = -INFINITY;
            }
            sc[f][0] = v0; sc[f][1] = v1; sc[f][2] = v2; sc[f][3] = v3;
            mx0 = fmaxf(mx0, fmaxf(v0, v1));
            mx1 = fmaxf(mx1, fmaxf(v2, v3));
        }
        mx0 = fmaxf(mx0, __shfl_xor_sync(0xffffffffu, mx0, 1));
        mx0 = fmaxf(mx0, __shfl_xor_sync(0xffffffffu, mx0, 2));
        mx1 = fmaxf(mx1, __shfl_xor_sync(0xffffffffu, mx1, 1));
        mx1 = fmaxf(mx1, __shfl_xor_sync(0xffffffffu, mx1, 2));

        float mn0 = fmaxf(m0, mx0), mn1 = fmaxf(m1, mx1);
        float cr0 = __expf(m0 - mn0), cr1 = __expf(m1 - mn1);
        m0 = mn0; m1 = mn1;
#pragma unroll
        for (int f = 0; f < 16; f++) {
            o[f][0] *= cr0; o[f][1] *= cr0;
            o[f][2] *= cr1; o[f][3] *= cr1;
        }
        float s0 = 0.f, s1 = 0.f;
#pragma unroll
        for (int f = 0; f < 8; f++) {
            float p0 = __expf(sc[f][0] - mn0);
            float p1 = __expf(sc[f][1] - mn0);
            float p2 = __expf(sc[f][2] - mn1);
            float p3 = __expf(sc[f][3] - mn1);
            sc[f][0] = p0; sc[f][1] = p1; sc[f][2] = p2; sc[f][3] = p3;
            s0 += p0 + p1; s1 += p2 + p3;
        }
        l0 = l0*cr0 + s0; l1 = l1*cr1 + s1;

        // ---- P @ V ----
#pragma unroll
        for (int kc = 0; kc < 4; kc++) {
            unsigned pa0 = h2pack(sc[2*kc][0],   sc[2*kc][1]);
            unsigned pa1 = h2pack(sc[2*kc][2],   sc[2*kc][3]);
            unsigned pa2 = h2pack(sc[2*kc+1][0], sc[2*kc+1][1]);
            unsigned pa3 = h2pack(sc[2*kc+1][2], sc[2*kc+1][3]);
#pragma unroll
            for (int g = 0; g < 8; g++) {
                unsigned v0, v1, v2, v3;
                LDSM4(v0, v1, v2, v3,
                      vt_lane + (unsigned)(g*16*VH*2 + kc*32));
                MMAF16(o[2*g],   pa0, pa1, pa2, pa3, v0, v1);
                MMAF16(o[2*g+1], pa0, pa1, pa2, pa3, v2, v3);
            }
        }
    }

    // ---- normalize & write fp16 [B,S,H*HD] ----
    l0 += __shfl_xor_sync(0xffffffffu, l0, 1);
    l0 += __shfl_xor_sync(0xffffffffu, l0, 2);
    l1 += __shfl_xor_sync(0xffffffffu, l1, 1);
    l1 += __shfl_xor_sync(0xffffffffu, l1, 2);
    float inv0 = 1.f / l0, inv1 = 1.f / l1;

    const int b = bh >> 4, h = bh & 15;
    const int row0 = q0 + wid*16 + a_;
    __half* op0 = g_aoh + ((size_t)(b*S_ + row0))     * D_ + h*HD_;
    __half* op1 = g_aoh + ((size_t)(b*S_ + row0 + 8)) * D_ + h*HD_;
#pragma unroll
    for (int f = 0; f < 16; f++) {
        int c = f*8 + q_*2;
        *(unsigned*)(op0 + c) = h2pack(o[f][0]*inv0, o[f][1]*inv0);
        *(unsigned*)(op1 + c) = h2pack(o[f][2]*inv1, o[f][3]*inv1);
    }
}

// =====================================================================
extern "C" void kernel_launch(void* const* d_in, const int* in_sizes, int n_in,
                              void* d_out, int out_size)
{
    (void)in_sizes; (void)n_in; (void)out_size;
    const float* x    = (const float*)d_in[0];
    // d_in[1] = mask: exactly causal, implemented analytically
    const float* cosT = (const float*)d_in[2];
    const float* sinT = (const float*)d_in[3];
    const float* Wq   = (const float*)d_in[4];
    const float* Wk   = (const float*)d_in[5];
    const float* Wv   = (const float*)d_in[6];
    const float* Wo   = (const float*)d_in[7];
    float* out = (float*)d_out;

    cudaFuncSetAttribute(gemm_h,
        cudaFuncAttributeMaxDynamicSharedMemorySize, GS);
    cudaFuncSetAttribute(attn_h,
        cudaFuncAttributeMaxDynamicSharedMemorySize, ATT3_SMEM);

    // 0) fp32 -> fp16 conversion of inputs (dst chosen device-side)
    f2h_kernel<<<(B_*S_*D_)/2048, 256>>>(x,  0);
    f2h_kernel<<<(D_*D_)/2048, 256>>>(Wq, 1);
    f2h_kernel<<<(D_*D_)/2048, 256>>>(Wk, 2);
    f2h_kernel<<<(D_*D_)/2048, 256>>>(Wv, 3);
    f2h_kernel<<<(D_*D_)/2048, 256>>>(Wo, 4);

    // 1) fused QKV projection -> fp16 [B,H,S,HD]
    dim3 gqkv(D_/TN, M_/TM, 3);
    gemm_h<<<gqkv, 256, GS>>>(nullptr, 0);

    // 2) RoPE in place on q,k (fp16)
    rope_h<<<(B_*H_*S_*16)/256, 256>>>(cosT, sinT);

    // 3) causal flash attention -> fp16 g_aoh [B,S,D]
    dim3 gatt(S_/128, B_*H_);
    attn_h<<<gatt, 256, ATT3_SMEM>>>();

    // 4) output projection -> fp32 d_out
    dim3 go(D_/TN, M_/TM, 1);
    gemm_h<<<go, 256, GS>>>(out, 1);
}

// round 13
// speedup vs baseline: 1.9779x; 1.1052x over previous
#include <cuda_runtime.h>
#include <cuda_fp16.h>
#include <math.h>

#define B_  2
#define S_  2048
#define D_  2048
#define H_  16
#define HD_ 128
#define M_  (B_*S_)          // 4096

#define SCALE_ 0.08838834764831845f   // 1/sqrt(128)

// -------- scratch (fp16, 16B-aligned via uint4 backing) --------
static __device__ uint4 g_qh_raw [B_*H_*S_*HD_/8];
static __device__ uint4 g_kh_raw [B_*H_*S_*HD_/8];
static __device__ uint4 g_vh_raw [B_*H_*S_*HD_/8];
static __device__ uint4 g_aoh_raw[B_*S_*D_/8];
static __device__ uint4 g_xh_raw [B_*S_*D_/8];
static __device__ uint4 g_wq_raw [D_*D_/8];
static __device__ uint4 g_wk_raw [D_*D_/8];
static __device__ uint4 g_wv_raw [D_*D_/8];
static __device__ uint4 g_wo_raw [D_*D_/8];
// device-side accessors ONLY (never touch these from host code!)
#define g_qh  ((__half*)g_qh_raw)
#define g_kh  ((__half*)g_kh_raw)
#define g_vh  ((__half*)g_vh_raw)
#define g_aoh ((__half*)g_aoh_raw)
#define g_xh  ((__half*)g_xh_raw)
#define g_wq  ((__half*)g_wq_raw)
#define g_wk  ((__half*)g_wk_raw)
#define g_wv  ((__half*)g_wv_raw)
#define g_wo  ((__half*)g_wo_raw)

// ===================== helpers =========================
__device__ __forceinline__ unsigned smem_u32(const void* p) {
    unsigned a;
    asm("{ .reg .u64 t; cvta.to.shared.u64 t, %1; cvt.u32.u64 %0, t; }"
        : "=r"(a) : "l"(p));
    return a;
}

#define LDSM4(r0,r1,r2,r3,a) \
    asm volatile("ldmatrix.sync.aligned.m8n8.x4.shared.b16 {%0,%1,%2,%3}, [%4];" \
        : "=r"(r0),"=r"(r1),"=r"(r2),"=r"(r3) : "r"(a))

#define MMAF16(d, a0,a1,a2,a3, b0,b1) \
    asm volatile("mma.sync.aligned.m16n8k16.row.col.f32.f16.f16.f32 " \
        "{%0,%1,%2,%3}, {%4,%5,%6,%7}, {%8,%9}, {%0,%1,%2,%3};" \
        : "+f"((d)[0]),"+f"((d)[1]),"+f"((d)[2]),"+f"((d)[3]) \
        : "r"(a0),"r"(a1),"r"(a2),"r"(a3),"r"(b0),"r"(b1))

#define CP16(dst, src) \
    asm volatile("cp.async.cg.shared.global [%0], [%1], 16;" \
                 :: "r"(dst), "l"(src) : "memory")
#define CP_COMMIT() asm volatile("cp.async.commit_group;" ::: "memory")
#define CP_WAIT0()  asm volatile("cp.async.wait_group 0;"  ::: "memory")

// pack two fp32 -> half2 (lo = first arg)
__device__ __forceinline__ unsigned h2pack(float lo, float hi) {
    unsigned r;
    asm("cvt.rn.f16x2.f32 %0, %1, %2;" : "=r"(r) : "f"(hi), "f"(lo));
    return r;
}
__device__ __forceinline__ float2 h2unpack(unsigned u) {
    __half2 h = *(__half2*)&u;
    return __half22float2(h);
}

// =====================================================================
// fp32 -> fp16 bulk convert; dst selected DEVICE-SIDE by `which`
// which: 0=x, 1=Wq, 2=Wk, 3=Wv, 4=Wo
// =====================================================================
__global__ void f2h_kernel(const float* __restrict__ src, int which)
{
    __half* dst = (which == 0) ? g_xh :
                  (which == 1) ? g_wq :
                  (which == 2) ? g_wk :
                  (which == 3) ? g_wv : g_wo;
    int i = (blockIdx.x * blockDim.x + threadIdx.x) * 8;
    float4 a = *(const float4*)(src + i);
    float4 b = *(const float4*)(src + i + 4);
    uint4 r;
    r.x = h2pack(a.x, a.y); r.y = h2pack(a.z, a.w);
    r.z = h2pack(b.x, b.y); r.w = h2pack(b.z, b.w);
    *(uint4*)(dst + i) = r;
}

// =====================================================================
// fp16 NT GEMM (fp32 accum): C[m,n] = sum_k A[m,k] * W[n,k].
// CTA tile 128x128, warp tile 32x64 (4x2 grid), BK=32, 256 threads,
// cp.async.cg 16B staging, double buffer 40KB, 2 CTA/SM.
// mode=0 (QKV): A=g_xh, W per blockIdx.z, scatter fp16 [B,H,S,HD]
// mode=1 (out): A=g_aoh, W=g_wo, write fp32 row-major to Cout
// =====================================================================
#define TM 128
#define TN 128
#define BKH 32
#define GNCH (D_/BKH)         // 64
#define HRS 40                // halves per row (80B; 16B-aligned rows)
#define ASZ (TM*HRS*2)        // 10240 B
#define BSZ (TN*HRS*2)        // 10240 B
#define BUF (ASZ+BSZ)         // 20480
#define GS  (2*BUF)           // 40960

__global__ __launch_bounds__(256, 2) void gemm_h(float* __restrict__ Cout, int mode)
{
    extern __shared__ char sm_[];
    const unsigned sbase = smem_u32(sm_);

    const int tid = threadIdx.x;
    const int wid = tid >> 5, lid = tid & 31;
    const int m0 = blockIdx.y * TM;
    const int n0 = blockIdx.x * TN;

    const __half* A;
    const __half* W;
    __half* outh = nullptr;
    if (mode == 0) {
        A = g_xh;
        W    = (blockIdx.z == 0) ? g_wq : (blockIdx.z == 1) ? g_wk : g_wv;
        outh = (blockIdx.z == 0) ? g_qh : (blockIdx.z == 1) ? g_kh : g_vh;
    } else {
        A = g_aoh;
        W = g_wo;
    }

    const int wm = wid >> 1, wn = wid & 1;   // warp tile rows wm*32, cols wn*64

    const unsigned aoff0 = (unsigned)(((wm*32 + (lid & 7) + ((lid & 8) ? 8 : 0)) * HRS
                                       + ((lid & 16) ? 8 : 0)) * 2);
    const unsigned boff0 = (unsigned)(((wn*64 + (lid & 7) + ((lid & 16) ? 8 : 0)) * HRS
                                       + ((lid & 8) ? 8 : 0)) * 2);

    // cp.async staging: rows tid>>2 and +64, 16B seg tid&3 (seg*8 halves)
    const int srow = tid >> 2, sseg = tid & 3;

    float acc[2][8][4];
#pragma unroll
    for (int mt = 0; mt < 2; mt++)
#pragma unroll
        for (int nt = 0; nt < 8; nt++)
#pragma unroll
            for (int e = 0; e < 4; e++) acc[mt][nt][e] = 0.f;

    // ---- prologue: async-load chunk 0 into buffer 0 ----
    {
        unsigned d = sbase;
#pragma unroll
        for (int i = 0; i < 2; i++) {
            int r = srow + i*64;
            CP16(d + (unsigned)((r*HRS + sseg*8)*2),
                 A + (size_t)(m0 + r) * D_ + sseg*8);
            CP16(d + ASZ + (unsigned)((r*HRS + sseg*8)*2),
                 W + (size_t)(n0 + r) * D_ + sseg*8);
        }
        CP_COMMIT(); CP_WAIT0();
    }
    __syncthreads();

#pragma unroll 1
    for (int c = 0; c < GNCH; c++) {
        // issue async copies for next chunk into the other buffer
        if (c + 1 < GNCH) {
            unsigned d = sbase + (unsigned)((c + 1) & 1) * BUF;
            int k0 = (c + 1) * BKH;
#pragma unroll
            for (int i = 0; i < 2; i++) {
                int r = srow + i*64;
                CP16(d + (unsigned)((r*HRS + sseg*8)*2),
                     A + (size_t)(m0 + r) * D_ + k0 + sseg*8);
                CP16(d + ASZ + (unsigned)((r*HRS + sseg*8)*2),
                     W + (size_t)(n0 + r) * D_ + k0 + sseg*8);
            }
            CP_COMMIT();
        }

        // ---- MMA over current buffer: 2 k16-steps ----
        const unsigned sA = sbase + (unsigned)(c & 1) * BUF;
        const unsigned sB = sA + ASZ;
#pragma unroll
        for (int ks = 0; ks < 2; ks++) {
            const unsigned kso = (unsigned)(ks * 32);   // 16 halves
            unsigned a0[2], a1[2], a2[2], a3[2];
#pragma unroll
            for (int mt = 0; mt < 2; mt++)
                LDSM4(a0[mt], a1[mt], a2[mt], a3[mt],
                      sA + aoff0 + (unsigned)(mt*16*HRS*2) + kso);
#pragma unroll
            for (int p = 0; p < 4; p++) {
                unsigned b0, b1, b2, b3;
                LDSM4(b0, b1, b2, b3,
                      sB + boff0 + (unsigned)(p*16*HRS*2) + kso);
#pragma unroll
                for (int mt = 0; mt < 2; mt++) {
                    MMAF16(acc[mt][2*p],   a0[mt], a1[mt], a2[mt], a3[mt], b0, b1);
                    MMAF16(acc[mt][2*p+1], a0[mt], a1[mt], a2[mt], a3[mt], b2, b3);
                }
            }
        }

        if (c + 1 < GNCH) CP_WAIT0();
        __syncthreads();
    }

    // ---- epilogue (c-frag: rows lid>>2 / +8, cols (lid&3)*2) ----
#pragma unroll
    for (int mt = 0; mt < 2; mt++)
#pragma unroll
    for (int nt = 0; nt < 8; nt++) {
        int r  = m0 + wm*32 + mt*16 + (lid >> 2);
        int cc = n0 + wn*64 + nt*8 + (lid & 3)*2;
        if (mode != 0) {
            *(float2*)(Cout + (size_t)r * D_ + cc) =
                make_float2(acc[mt][nt][0], acc[mt][nt][1]);
            *(float2*)(Cout + (size_t)(r + 8) * D_ + cc) =
                make_float2(acc[mt][nt][2], acc[mt][nt][3]);
        } else {
            int h = cc >> 7, cd = cc & 127;
            int b1 = r >> 11, s1 = r & (S_ - 1);
            *(unsigned*)(outh + ((size_t)(b1*H_ + h) * S_ + s1) * HD_ + cd) =
                h2pack(acc[mt][nt][0], acc[mt][nt][1]);
            int r2 = r + 8;
            int b2 = r2 >> 11, s2 = r2 & (S_ - 1);
            *(unsigned*)(outh + ((size_t)(b2*H_ + h) * S_ + s2) * HD_ + cd) =
                h2pack(acc[mt][nt][2], acc[mt][nt][3]);
        }
    }
}

// =====================================================================
// RoPE in-place on fp16 g_qh, g_kh (compute fp32, 4 d-values / thread).
// =====================================================================
__global__ void rope_h(const float* __restrict__ cosT,
                       const float* __restrict__ sinT)
{
    int idx = blockIdx.x * blockDim.x + threadIdx.x;   // over B*H*S*16
    int d4 = (idx & 15) << 2;
    int s  = (idx >> 4) & (S_ - 1);
    int bh = idx >> 15;
    size_t base = ((size_t)bh * S_ + s) * HD_;
    float4 c  = *(const float4*)&cosT[s*HD_ + d4];
    float4 sn = *(const float4*)&sinT[s*HD_ + d4];

    uint2 q1u = *(uint2*)(g_qh + base + d4);
    uint2 q2u = *(uint2*)(g_qh + base + d4 + 64);
    float2 q1a = h2unpack(q1u.x), q1b = h2unpack(q1u.y);
    float2 q2a = h2unpack(q2u.x), q2b = h2unpack(q2u.y);
    uint2 o1, o2;
    o1.x = h2pack(q1a.x*c.x - q2a.x*sn.x, q1a.y*c.y - q2a.y*sn.y);
    o1.y = h2pack(q1b.x*c.z - q2b.x*sn.z, q1b.y*c.w - q2b.y*sn.w);
    o2.x = h2pack(q2a.x*c.x + q1a.x*sn.x, q2a.y*c.y + q1a.y*sn.y);
    o2.y = h2pack(q2b.x*c.z + q1b.x*sn.z, q2b.y*c.w + q1b.y*sn.w);
    *(uint2*)(g_qh + base + d4)      = o1;
    *(uint2*)(g_qh + base + d4 + 64) = o2;

    uint2 k1u = *(uint2*)(g_kh + base + d4);
    uint2 k2u = *(uint2*)(g_kh + base + d4 + 64);
    float2 k1a = h2unpack(k1u.x), k1b = h2unpack(k1u.y);
    float2 k2a = h2unpack(k2u.x), k2b = h2unpack(k2u.y);
    o1.x = h2pack(k1a.x*c.x - k2a.x*sn.x, k1a.y*c.y - k2a.y*sn.y);
    o1.y = h2pack(k1b.x*c.z - k2b.x*sn.z, k1b.y*c.w - k2b.y*sn.w);
    o2.x = h2pack(k2a.x*c.x + k1a.x*sn.x, k2a.y*c.y + k1a.y*sn.y);
    o2.y = h2pack(k2b.x*c.z + k1b.x*sn.z, k2b.y*c.w + k1b.y*sn.w);
    *(uint2*)(g_kh + base + d4)      = o1;
    *(uint2*)(g_kh + base + d4 + 64) = o2;
}

// =====================================================================
// Flash attention on fp16 tensor cores (fp32 accum). BQ=128, BK=64,
// 8 warps, P in registers (frag layout identity). fp16 in/out.
// (unchanged from R12)
// =====================================================================
#define QH 136
#define VH 72
#define KS_OFFH (128*QH)
#define VT_OFFH (KS_OFFH + 64*QH)
#define ATT3_SMEM ((VT_OFFH + 128*VH) * 2)   // 70656 bytes

__global__ __launch_bounds__(256, 1) void attn_h()
{
    extern __shared__ __half hsm[];
    __half* Qs = hsm;
    __half* Ks = hsm + KS_OFFH;
    __half* VT = hsm + VT_OFFH;

    const int tid = threadIdx.x;
    const int wid = tid >> 5, lid = tid & 31;
    const int qb  = 15 - (int)blockIdx.x;
    const int bh  = blockIdx.y;
    const int q0  = qb * 128;

    const __half* qph = g_qh + (size_t)bh * S_ * HD_;
    const __half* kph = g_kh + (size_t)bh * S_ * HD_;
    const __half* vph = g_vh + (size_t)bh * S_ * HD_;

    // ---- load Q tile (direct fp16 copy, 16B segs) ----
#pragma unroll
    for (int i = 0; i < 8; i++) {
        int pos = i*256 + tid;            // 2048 segs
        int row = pos >> 4;
        int seg = pos & 15;
        *(uint4*)(Qs + row*QH + seg*8) =
            *(const uint4*)(qph + (size_t)(q0 + row) * HD_ + seg*8);
    }

    const int a_ = lid >> 2, q_ = lid & 3;
    const int r0g = q0 + wid*16 + a_;

    const unsigned aq_base = smem_u32(Qs) +
        (unsigned)(((wid*16 + (lid & 7) + ((lid & 8) ? 8 : 0)) * QH
                    + ((lid & 16) ? 8 : 0)) * 2);
    const unsigned ks_lane = smem_u32(Ks) +
        (unsigned)((((lid & 7) + ((lid & 16) ? 8 : 0)) * QH
                    + ((lid & 8) ? 8 : 0)) * 2);
    const unsigned vt_lane = smem_u32(VT) +
        (unsigned)((((lid & 7) + ((lid & 16) ? 8 : 0)) * VH
                    + ((lid & 8) ? 8 : 0)) * 2);

    float m0 = -INFINITY, m1 = -INFINITY, l0 = 0.f, l1 = 0.f;
    float o[16][4];
#pragma unroll
    for (int f = 0; f < 16; f++)
#pragma unroll
        for (int e = 0; e < 4; e++) o[f][e] = 0.f;

    const int nt = 2*qb + 2;
#pragma unroll 1
    for (int t = 0; t < nt; t++) {
        const int kb = t * 64;
        __syncthreads();
        // ---- stage K (row-major) and V (transposed) ----
#pragma unroll
        for (int i = 0; i < 4; i++) {
            int pos = i*256 + tid;        // 1024 segs
            int row = pos >> 4;
            int seg = pos & 15;
            *(uint4*)(Ks + row*QH + seg*8) =
                *(const uint4*)(kph + (size_t)(kb + row) * HD_ + seg*8);
        }
#pragma unroll
        for (int i = 0; i < 32; i++) {
            int pos = i*256 + tid;        // 8192 scalars
            int key = pos >> 7, hd = pos & 127;
            VT[hd*VH + key] = vph[(size_t)(kb + key) * HD_ + hd];
        }
        __syncthreads();

        // ---- QK^T ----
        float sc[8][4];
#pragma unroll
        for (int f = 0; f < 8; f++)
#pragma unroll
            for (int e = 0; e < 4; e++) sc[f][e] = 0.f;

#pragma unroll
        for (int kc = 0; kc < 8; kc++) {
            unsigned a0, a1, a2, a3;
            LDSM4(a0, a1, a2, a3, aq_base + (unsigned)(kc*32));
#pragma unroll
            for (int p = 0; p < 4; p++) {
                unsigned b0, b1, b2, b3;
                LDSM4(b0, b1, b2, b3,
                      ks_lane + (unsigned)(p*16*QH*2 + kc*32));
                MMAF16(sc[2*p],   a0, a1, a2, a3, b0, b1);
                MMAF16(sc[2*p+1], a0, a1, a2, a3, b2, b3);
            }
        }

        // ---- online softmax ----
        const bool maskt = (kb + 63 > q0);
        float mx0 = -INFINITY, mx1 = -INFINITY;
#pragma unroll
        for (int f = 0; f < 8; f++) {
            int cg = kb + f*8 + q_*2;
            float v0 = sc[f][0]*SCALE_, v1 = sc[f][1]*SCALE_;
            float v2 = sc[f][2]*SCALE_, v3 = sc[f][3]*SCALE_;
            if (maskt) {
                if (cg     > r0g)     v0 = -INFINITY;
                if (cg + 1 > r0g)     v1 = -INFINITY;
                if (cg     > r0g + 8) v2 = -INFINITY;
                if (cg + 1 > r0g + 8) v3 = -INFINITY;
            }
            sc[f][0] = v0; sc[f][1] = v1; sc[f][2] = v2; sc[f][3] = v3;
            mx0 = fmaxf(mx0, fmaxf(v0, v1));
            mx1 = fmaxf(mx1, fmaxf(v2, v3));
        }
        mx0 = fmaxf(mx0, __shfl_xor_sync(0xffffffffu, mx0, 1));
        mx0 = fmaxf(mx0, __shfl_xor_sync(0xffffffffu, mx0, 2));
        mx1 = fmaxf(mx1, __shfl_xor_sync(0xffffffffu, mx1, 1));
        mx1 = fmaxf(mx1, __shfl_xor_sync(0xffffffffu, mx1, 2));

        float mn0 = fmaxf(m0, mx0), mn1 = fmaxf(m1, mx1);
        float cr0 = __expf(m0 - mn0), cr1 = __expf(m1 - mn1);
        m0 = mn0; m1 = mn1;
#pragma unroll
        for (int f = 0; f < 16; f++) {
            o[f][0] *= cr0; o[f][1] *= cr0;
            o[f][2] *= cr1; o[f][3] *= cr1;
        }
        float s0 = 0.f, s1 = 0.f;
#pragma unroll
        for (int f = 0; f < 8; f++) {
            float p0 = __expf(sc[f][0] - mn0);
            float p1 = __expf(sc[f][1] - mn0);
            float p2 = __expf(sc[f][2] - mn1);
            float p3 = __expf(sc[f][3] - mn1);
            sc[f][0] = p0; sc[f][1] = p1; sc[f][2] = p2; sc[f][3] = p3;
            s0 += p0 + p1; s1 += p2 + p3;
        }
        l0 = l0*cr0 + s0; l1 = l1*cr1 + s1;

        // ---- P @ V ----
#pragma unroll
        for (int kc = 0; kc < 4; kc++) {
            unsigned pa0 = h2pack(sc[2*kc][0],   sc[2*kc][1]);
            unsigned pa1 = h2pack(sc[2*kc][2],   sc[2*kc][3]);
            unsigned pa2 = h2pack(sc[2*kc+1][0], sc[2*kc+1][1]);
            unsigned pa3 = h2pack(sc[2*kc+1][2], sc[2*kc+1][3]);
#pragma unroll
            for (int g = 0; g < 8; g++) {
                unsigned v0, v1, v2, v3;
                LDSM4(v0, v1, v2, v3,
                      vt_lane + (unsigned)(g*16*VH*2 + kc*32));
                MMAF16(o[2*g],   pa0, pa1, pa2, pa3, v0, v1);
                MMAF16(o[2*g+1], pa0, pa1, pa2, pa3, v2, v3);
            }
        }
    }

    // ---- normalize & write fp16 [B,S,H*HD] ----
    l0 += __shfl_xor_sync(0xffffffffu, l0, 1);
    l0 += __shfl_xor_sync(0xffffffffu, l0, 2);
    l1 += __shfl_xor_sync(0xffffffffu, l1, 1);
    l1 += __shfl_xor_sync(0xffffffffu, l1, 2);
    float inv0 = 1.f / l0, inv1 = 1.f / l1;

    const int b = bh >> 4, h = bh & 15;
    const int row0 = q0 + wid*16 + a_;
    __half* op0 = g_aoh + ((size_t)(b*S_ + row0))     * D_ + h*HD_;
    __half* op1 = g_aoh + ((size_t)(b*S_ + row0 + 8)) * D_ + h*HD_;
#pragma unroll
    for (int f = 0; f < 16; f++) {
        int c = f*8 + q_*2;
        *(unsigned*)(op0 + c) = h2pack(o[f][0]*inv0, o[f][1]*inv0);
        *(unsigned*)(op1 + c) = h2pack(o[f][2]*inv1, o[f][3]*inv1);
    }
}

// =====================================================================
extern "C" void kernel_launch(void* const* d_in, const int* in_sizes, int n_in,
                              void* d_out, int out_size)
{
    (void)in_sizes; (void)n_in; (void)out_size;
    const float* x    = (const float*)d_in[0];
    // d_in[1] = mask: exactly causal, implemented analytically
    const float* cosT = (const float*)d_in[2];
    const float* sinT = (const float*)d_in[3];
    const float* Wq   = (const float*)d_in[4];
    const float* Wk   = (const float*)d_in[5];
    const float* Wv   = (const float*)d_in[6];
    const float* Wo   = (const float*)d_in[7];
    float* out = (float*)d_out;

    cudaFuncSetAttribute(gemm_h,
        cudaFuncAttributeMaxDynamicSharedMemorySize, GS);
    cudaFuncSetAttribute(attn_h,
        cudaFuncAttributeMaxDynamicSharedMemorySize, ATT3_SMEM);

    // 0) fp32 -> fp16 conversion of inputs (dst chosen device-side)
    f2h_kernel<<<(B_*S_*D_)/2048, 256>>>(x,  0);
    f2h_kernel<<<(D_*D_)/2048, 256>>>(Wq, 1);
    f2h_kernel<<<(D_*D_)/2048, 256>>>(Wk, 2);
    f2h_kernel<<<(D_*D_)/2048, 256>>>(Wv, 3);
    f2h_kernel<<<(D_*D_)/2048, 256>>>(Wo, 4);

    // 1) fused QKV projection -> fp16 [B,H,S,HD]
    dim3 gqkv(D_/TN, M_/TM, 3);
    gemm_h<<<gqkv, 256, GS>>>(nullptr, 0);

    // 2) RoPE in place on q,k (fp16)
    rope_h<<<(B_*H_*S_*16)/256, 256>>>(cosT, sinT);

    // 3) causal flash attention -> fp16 g_aoh [B,S,D]
    dim3 gatt(S_/128, B_*H_);
    attn_h<<<gatt, 256, ATT3_SMEM>>>();

    // 4) output projection -> fp32 d_out
    dim3 go(D_/TN, M_/TM, 1);
    gemm_h<<<go, 256, GS>>>(out, 1);
}

// round 14
// speedup vs baseline: 1.9843x; 1.0032x over previous
#include <cuda_runtime.h>
#include <cuda_fp16.h>
#include <math.h>

#define B_  2
#define S_  2048
#define D_  2048
#define H_  16
#define HD_ 128
#define M_  (B_*S_)          // 4096

#define SCALE_ 0.08838834764831845f   // 1/sqrt(128)

// -------- scratch (fp16, 16B-aligned via uint4 backing) --------
static __device__ uint4 g_qh_raw [B_*H_*S_*HD_/8];
static __device__ uint4 g_kh_raw [B_*H_*S_*HD_/8];
static __device__ uint4 g_vh_raw [B_*H_*S_*HD_/8];
static __device__ uint4 g_aoh_raw[B_*S_*D_/8];
static __device__ uint4 g_xh_raw [B_*S_*D_/8];
static __device__ uint4 g_wq_raw [D_*D_/8];
static __device__ uint4 g_wk_raw [D_*D_/8];
static __device__ uint4 g_wv_raw [D_*D_/8];
static __device__ uint4 g_wo_raw [D_*D_/8];
// device-side accessors ONLY (never touch these from host code!)
#define g_qh  ((__half*)g_qh_raw)
#define g_kh  ((__half*)g_kh_raw)
#define g_vh  ((__half*)g_vh_raw)
#define g_aoh ((__half*)g_aoh_raw)
#define g_xh  ((__half*)g_xh_raw)
#define g_wq  ((__half*)g_wq_raw)
#define g_wk  ((__half*)g_wk_raw)
#define g_wv  ((__half*)g_wv_raw)
#define g_wo  ((__half*)g_wo_raw)

// ===================== helpers =========================
__device__ __forceinline__ unsigned smem_u32(const void* p) {
    unsigned a;
    asm("{ .reg .u64 t; cvta.to.shared.u64 t, %1; cvt.u32.u64 %0, t; }"
        : "=r"(a) : "l"(p));
    return a;
}

#define LDSM4(r0,r1,r2,r3,a) \
    asm volatile("ldmatrix.sync.aligned.m8n8.x4.shared.b16 {%0,%1,%2,%3}, [%4];" \
        : "=r"(r0),"=r"(r1),"=r"(r2),"=r"(r3) : "r"(a))

#define MMAF16(d, a0,a1,a2,a3, b0,b1) \
    asm volatile("mma.sync.aligned.m16n8k16.row.col.f32.f16.f16.f32 " \
        "{%0,%1,%2,%3}, {%4,%5,%6,%7}, {%8,%9}, {%0,%1,%2,%3};" \
        : "+f"((d)[0]),"+f"((d)[1]),"+f"((d)[2]),"+f"((d)[3]) \
        : "r"(a0),"r"(a1),"r"(a2),"r"(a3),"r"(b0),"r"(b1))

#define CP16(dst, src) \
    asm volatile("cp.async.cg.shared.global [%0], [%1], 16;" \
                 :: "r"(dst), "l"(src) : "memory")
#define CP_COMMIT() asm volatile("cp.async.commit_group;" ::: "memory")
#define CP_WAIT0()  asm volatile("cp.async.wait_group 0;"  ::: "memory")
#define CP_WAIT1()  asm volatile("cp.async.wait_group 1;"  ::: "memory")

// pack two fp32 -> half2 (lo = first arg)
__device__ __forceinline__ unsigned h2pack(float lo, float hi) {
    unsigned r;
    asm("cvt.rn.f16x2.f32 %0, %1, %2;" : "=r"(r) : "f"(hi), "f"(lo));
    return r;
}
__device__ __forceinline__ float2 h2unpack(unsigned u) {
    __half2 h = *(__half2*)&u;
    return __half22float2(h);
}

// =====================================================================
// fp32 -> fp16 bulk convert; dst selected DEVICE-SIDE by `which`
// which: 0=x, 1=Wq, 2=Wk, 3=Wv, 4=Wo
// =====================================================================
__global__ void f2h_kernel(const float* __restrict__ src, int which)
{
    __half* dst = (which == 0) ? g_xh :
                  (which == 1) ? g_wq :
                  (which == 2) ? g_wk :
                  (which == 3) ? g_wv : g_wo;
    int i = (blockIdx.x * blockDim.x + threadIdx.x) * 8;
    float4 a = *(const float4*)(src + i);
    float4 b = *(const float4*)(src + i + 4);
    uint4 r;
    r.x = h2pack(a.x, a.y); r.y = h2pack(a.z, a.w);
    r.z = h2pack(b.x, b.y); r.w = h2pack(b.z, b.w);
    *(uint4*)(dst + i) = r;
}

// =====================================================================
// fp16 NT GEMM (fp32 accum): C[m,n] = sum_k A[m,k] * W[n,k].
// CTA tile 128x128, warp tile 32x64 (4x2 grid), BK=32, 256 threads,
// cp.async.cg 16B staging, 3-STAGE pipeline (61.4KB), 2 CTA/SM.
// mode=0 (QKV): A=g_xh, W per blockIdx.z, scatter fp16 [B,H,S,HD]
// mode=1 (out): A=g_aoh, W=g_wo, write fp32 row-major to Cout
// =====================================================================
#define TM 128
#define TN 128
#define BKH 32
#define GNCH (D_/BKH)         // 64
#define HRS 40                // halves per row (80B; 16B-aligned rows)
#define ASZ (TM*HRS*2)        // 10240 B
#define BSZ (TN*HRS*2)        // 10240 B
#define BUF (ASZ+BSZ)         // 20480
#define NSTG 3
#define GS  (NSTG*BUF)        // 61440

__global__ __launch_bounds__(256, 2) void gemm_h(float* __restrict__ Cout, int mode)
{
    extern __shared__ char sm_[];
    const unsigned sbase = smem_u32(sm_);

    const int tid = threadIdx.x;
    const int wid = tid >> 5, lid = tid & 31;
    const int m0 = blockIdx.y * TM;
    const int n0 = blockIdx.x * TN;

    const __half* A;
    const __half* W;
    __half* outh = nullptr;
    if (mode == 0) {
        A = g_xh;
        W    = (blockIdx.z == 0) ? g_wq : (blockIdx.z == 1) ? g_wk : g_wv;
        outh = (blockIdx.z == 0) ? g_qh : (blockIdx.z == 1) ? g_kh : g_vh;
    } else {
        A = g_aoh;
        W = g_wo;
    }

    const int wm = wid >> 1, wn = wid & 1;   // warp tile rows wm*32, cols wn*64

    const unsigned aoff0 = (unsigned)(((wm*32 + (lid & 7) + ((lid & 8) ? 8 : 0)) * HRS
                                       + ((lid & 16) ? 8 : 0)) * 2);
    const unsigned boff0 = (unsigned)(((wn*64 + (lid & 7) + ((lid & 16) ? 8 : 0)) * HRS
                                       + ((lid & 8) ? 8 : 0)) * 2);

    // cp.async staging: rows tid>>2 and +64, 16B seg tid&3 (seg*8 halves)
    const int srow = tid >> 2, sseg = tid & 3;

    float acc[2][8][4];
#pragma unroll
    for (int mt = 0; mt < 2; mt++)
#pragma unroll
        for (int nt = 0; nt < 8; nt++)
#pragma unroll
            for (int e = 0; e < 4; e++) acc[mt][nt][e] = 0.f;

    // ---- prologue: async-load chunks 0 and 1 ----
#pragma unroll
    for (int pc = 0; pc < 2; pc++) {
        unsigned d = sbase + (unsigned)pc * BUF;
        int k0 = pc * BKH;
#pragma unroll
        for (int i = 0; i < 2; i++) {
            int r = srow + i*64;
            CP16(d + (unsigned)((r*HRS + sseg*8)*2),
                 A + (size_t)(m0 + r) * D_ + k0 + sseg*8);
            CP16(d + ASZ + (unsigned)((r*HRS + sseg*8)*2),
                 W + (size_t)(n0 + r) * D_ + k0 + sseg*8);
        }
        CP_COMMIT();
    }
    CP_WAIT1();       // chunk 0 resident
    __syncthreads();

#pragma unroll 1
    for (int c = 0; c < GNCH; c++) {
        // issue async copies for chunk c+2 (keep 2 chunks in flight)
        const int ci2 = c + 2;
        if (ci2 < GNCH) {
            unsigned d = sbase + (unsigned)(ci2 % NSTG) * BUF;
            int k0 = ci2 * BKH;
#pragma unroll
            for (int i = 0; i < 2; i++) {
                int r = srow + i*64;
                CP16(d + (unsigned)((r*HRS + sseg*8)*2),
                     A + (size_t)(m0 + r) * D_ + k0 + sseg*8);
                CP16(d + ASZ + (unsigned)((r*HRS + sseg*8)*2),
                     W + (size_t)(n0 + r) * D_ + k0 + sseg*8);
            }
            CP_COMMIT();
        }

        // ---- MMA over chunk c: 2 k16-steps ----
        const unsigned sA = sbase + (unsigned)(c % NSTG) * BUF;
        const unsigned sB = sA + ASZ;
#pragma unroll
        for (int ks = 0; ks < 2; ks++) {
            const unsigned kso = (unsigned)(ks * 32);   // 16 halves
            unsigned a0[2], a1[2], a2[2], a3[2];
#pragma unroll
            for (int mt = 0; mt < 2; mt++)
                LDSM4(a0[mt], a1[mt], a2[mt], a3[mt],
                      sA + aoff0 + (unsigned)(mt*16*HRS*2) + kso);
#pragma unroll
            for (int p = 0; p < 4; p++) {
                unsigned b0, b1, b2, b3;
                LDSM4(b0, b1, b2, b3,
                      sB + boff0 + (unsigned)(p*16*HRS*2) + kso);
#pragma unroll
                for (int mt = 0; mt < 2; mt++) {
                    MMAF16(acc[mt][2*p],   a0[mt], a1[mt], a2[mt], a3[mt], b0, b1);
                    MMAF16(acc[mt][2*p+1], a0[mt], a1[mt], a2[mt], a3[mt], b2, b3);
                }
            }
        }

        // ensure chunk c+1 is resident before next iteration
        if (ci2 < GNCH)            CP_WAIT1();
        else if (c + 1 < GNCH)     CP_WAIT0();
        __syncthreads();
    }

    // ---- epilogue (c-frag: rows lid>>2 / +8, cols (lid&3)*2) ----
#pragma unroll
    for (int mt = 0; mt < 2; mt++)
#pragma unroll
    for (int nt = 0; nt < 8; nt++) {
        int r  = m0 + wm*32 + mt*16 + (lid >> 2);
        int cc = n0 + wn*64 + nt*8 + (lid & 3)*2;
        if (mode != 0) {
            *(float2*)(Cout + (size_t)r * D_ + cc) =
                make_float2(acc[mt][nt][0], acc[mt][nt][1]);
            *(float2*)(Cout + (size_t)(r + 8) * D_ + cc) =
                make_float2(acc[mt][nt][2], acc[mt][nt][3]);
        } else {
            int h = cc >> 7, cd = cc & 127;
            int b1 = r >> 11, s1 = r & (S_ - 1);
            *(unsigned*)(outh + ((size_t)(b1*H_ + h) * S_ + s1) * HD_ + cd) =
                h2pack(acc[mt][nt][0], acc[mt][nt][1]);
            int r2 = r + 8;
            int b2 = r2 >> 11, s2 = r2 & (S_ - 1);
            *(unsigned*)(outh + ((size_t)(b2*H_ + h) * S_ + s2) * HD_ + cd) =
                h2pack(acc[mt][nt][2], acc[mt][nt][3]);
        }
    }
}

// =====================================================================
// RoPE in-place on fp16 g_qh, g_kh (compute fp32, 4 d-values / thread).
// =====================================================================
__global__ void rope_h(const float* __restrict__ cosT,
                       const float* __restrict__ sinT)
{
    int idx = blockIdx.x * blockDim.x + threadIdx.x;   // over B*H*S*16
    int d4 = (idx & 15) << 2;
    int s  = (idx >> 4) & (S_ - 1);
    int bh = idx >> 15;
    size_t base = ((size_t)bh * S_ + s) * HD_;
    float4 c  = *(const float4*)&cosT[s*HD_ + d4];
    float4 sn = *(const float4*)&sinT[s*HD_ + d4];

    uint2 q1u = *(uint2*)(g_qh + base + d4);
    uint2 q2u = *(uint2*)(g_qh + base + d4 + 64);
    float2 q1a = h2unpack(q1u.x), q1b = h2unpack(q1u.y);
    float2 q2a = h2unpack(q2u.x), q2b = h2unpack(q2u.y);
    uint2 o1, o2;
    o1.x = h2pack(q1a.x*c.x - q2a.x*sn.x, q1a.y*c.y - q2a.y*sn.y);
    o1.y = h2pack(q1b.x*c.z - q2b.x*sn.z, q1b.y*c.w - q2b.y*sn.w);
    o2.x = h2pack(q2a.x*c.x + q1a.x*sn.x, q2a.y*c.y + q1a.y*sn.y);
    o2.y = h2pack(q2b.x*c.z + q1b.x*sn.z, q2b.y*c.w + q1b.y*sn.w);
    *(uint2*)(g_qh + base + d4)      = o1;
    *(uint2*)(g_qh + base + d4 + 64) = o2;

    uint2 k1u = *(uint2*)(g_kh + base + d4);
    uint2 k2u = *(uint2*)(g_kh + base + d4 + 64);
    float2 k1a = h2unpack(k1u.x), k1b = h2unpack(k1u.y);
    float2 k2a = h2unpack(k2u.x), k2b = h2unpack(k2u.y);
    o1.x = h2pack(k1a.x*c.x - k2a.x*sn.x, k1a.y*c.y - k2a.y*sn.y);
    o1.y = h2pack(k1b.x*c.z - k2b.x*sn.z, k1b.y*c.w - k2b.y*sn.w);
    o2.x = h2pack(k2a.x*c.x + k1a.x*sn.x, k2a.y*c.y + k1a.y*sn.y);
    o2.y = h2pack(k2b.x*c.z + k1b.x*sn.z, k2b.y*c.w + k1b.y*sn.w);
    *(uint2*)(g_kh + base + d4)      = o1;
    *(uint2*)(g_kh + base + d4 + 64) = o2;
}

// =====================================================================
// Flash attention on fp16 tensor cores (fp32 accum). BQ=128, BK=64,
// 8 warps, P in registers (frag layout identity). fp16 in/out.
// (unchanged from R13)
// =====================================================================
#define QH 136
#define VH 72
#define KS_OFFH (128*QH)
#define VT_OFFH (KS_OFFH + 64*QH)
#define ATT3_SMEM ((VT_OFFH + 128*VH) * 2)   // 70656 bytes

__global__ __launch_bounds__(256, 1) void attn_h()
{
    extern __shared__ __half hsm[];
    __half* Qs = hsm;
    __half* Ks = hsm + KS_OFFH;
    __half* VT = hsm + VT_OFFH;

    const int tid = threadIdx.x;
    const int wid = tid >> 5, lid = tid & 31;
    const int qb  = 15 - (int)blockIdx.x;
    const int bh  = blockIdx.y;
    const int q0  = qb * 128;

    const __half* qph = g_qh + (size_t)bh * S_ * HD_;
    const __half* kph = g_kh + (size_t)bh * S_ * HD_;
    const __half* vph = g_vh + (size_t)bh * S_ * HD_;

    // ---- load Q tile (direct fp16 copy, 16B segs) ----
#pragma unroll
    for (int i = 0; i < 8; i++) {
        int pos = i*256 + tid;            // 2048 segs
        int row = pos >> 4;
        int seg = pos & 15;
        *(uint4*)(Qs + row*QH + seg*8) =
            *(const uint4*)(qph + (size_t)(q0 + row) * HD_ + seg*8);
    }

    const int a_ = lid >> 2, q_ = lid & 3;
    const int r0g = q0 + wid*16 + a_;

    const unsigned aq_base = smem_u32(Qs) +
        (unsigned)(((wid*16 + (lid & 7) + ((lid & 8) ? 8 : 0)) * QH
                    + ((lid & 16) ? 8 : 0)) * 2);
    const unsigned ks_lane = smem_u32(Ks) +
        (unsigned)((((lid & 7) + ((lid & 16) ? 8 : 0)) * QH
                    + ((lid & 8) ? 8 : 0)) * 2);
    const unsigned vt_lane = smem_u32(VT) +
        (unsigned)((((lid & 7) + ((lid & 16) ? 8 : 0)) * VH
                    + ((lid & 8) ? 8 : 0)) * 2);

    float m0 = -INFINITY, m1 = -INFINITY, l0 = 0.f, l1 = 0.f;
    float o[16][4];
#pragma unroll
    for (int f = 0; f < 16; f++)
#pragma unroll
        for (int e = 0; e < 4; e++) o[f][e] = 0.f;

    const int nt = 2*qb + 2;
#pragma unroll 1
    for (int t = 0; t < nt; t++) {
        const int kb = t * 64;
        __syncthreads();
        // ---- stage K (row-major) and V (transposed) ----
#pragma unroll
        for (int i = 0; i < 4; i++) {
            int pos = i*256 + tid;        // 1024 segs
            int row = pos >> 4;
            int seg = pos & 15;
            *(uint4*)(Ks + row*QH + seg*8) =
                *(const uint4*)(kph + (size_t)(kb + row) * HD_ + seg*8);
        }
#pragma unroll
        for (int i = 0; i < 32; i++) {
            int pos = i*256 + tid;        // 8192 scalars
            int key = pos >> 7, hd = pos & 127;
            VT[hd*VH + key] = vph[(size_t)(kb + key) * HD_ + hd];
        }
        __syncthreads();

        // ---- QK^T ----
        float sc[8][4];
#pragma unroll
        for (int f = 0; f < 8; f++)
#pragma unroll
            for (int e = 0; e < 4; e++) sc[f][e] = 0.f;

#pragma unroll
        for (int kc = 0; kc < 8; kc++) {
            unsigned a0, a1, a2, a3;
            LDSM4(a0, a1, a2, a3, aq_base + (unsigned)(kc*32));
#pragma unroll
            for (int p = 0; p < 4; p++) {
                unsigned b0, b1, b2, b3;
                LDSM4(b0, b1, b2, b3,
                      ks_lane + (unsigned)(p*16*QH*2 + kc*32));
                MMAF16(sc[2*p],   a0, a1, a2, a3, b0, b1);
                MMAF16(sc[2*p+1], a0, a1, a2, a3, b2, b3);
            }
        }

        // ---- online softmax ----
        const bool maskt = (kb + 63 > q0);
        float mx0 = -INFINITY, mx1 = -INFINITY;
#pragma unroll
        for (int f = 0; f < 8; f++) {
            int cg = kb + f*8 + q_*2;
            float v0 = sc[f][0]*SCALE_, v1 = sc[f][1]*SCALE_;
            float v2 = sc[f][2]*SCALE_, v3 = sc[f][3]*SCALE_;
            if (maskt) {
                if (cg     > r0g)     v0 = -INFINITY;
                if (cg + 1 > r0g)     v1 = -INFINITY;
                if (cg     > r0g + 8) v2 = -INFINITY;
                if (cg + 1 > r0g + 8) v3 = -INFINITY;
            }
            sc[f][0] = v0; sc[f][1] = v1; sc[f][2] = v2; sc[f][3] = v3;
            mx0 = fmaxf(mx0, fmaxf(v0, v1));
            mx1 = fmaxf(mx1, fmaxf(v2, v3));
        }
        mx0 = fmaxf(mx0, __shfl_xor_sync(0xffffffffu, mx0, 1));
        mx0 = fmaxf(mx0, __shfl_xor_sync(0xffffffffu, mx0, 2));
        mx1 = fmaxf(mx1, __shfl_xor_sync(0xffffffffu, mx1, 1));
        mx1 = fmaxf(mx1, __shfl_xor_sync(0xffffffffu, mx1, 2));

        float mn0 = fmaxf(m0, mx0), mn1 = fmaxf(m1, mx1);
        float cr0 = __expf(m0 - mn0), cr1 = __expf(m1 - mn1);
        m0 = mn0; m1 = mn1;
#pragma unroll
        for (int f = 0; f < 16; f++) {
            o[f][0] *= cr0; o[f][1] *= cr0;
            o[f][2] *= cr1; o[f][3] *= cr1;
        }
        float s0 = 0.f, s1 = 0.f;
#pragma unroll
        for (int f = 0; f < 8; f++) {
            float p0 = __expf(sc[f][0] - mn0);
            float p1 = __expf(sc[f][1] - mn0);
            float p2 = __expf(sc[f][2] - mn1);
            float p3 = __expf(sc[f][3] - mn1);
            sc[f][0] = p0; sc[f][1] = p1; sc[f][2] = p2; sc[f][3] = p3;
            s0 += p0 + p1; s1 += p2 + p3;
        }
        l0 = l0*cr0 + s0; l1 = l1*cr1 + s1;

        // ---- P @ V ----
#pragma unroll
        for (int kc = 0; kc < 4; kc++) {
            unsigned pa0 = h2pack(sc[2*kc][0],   sc[2*kc][1]);
            unsigned pa1 = h2pack(sc[2*kc][2],   sc[2*kc][3]);
            unsigned pa2 = h2pack(sc[2*kc+1][0], sc[2*kc+1][1]);
            unsigned pa3 = h2pack(sc[2*kc+1][2], sc[2*kc+1][3]);
#pragma unroll
            for (int g = 0; g < 8; g++) {
                unsigned v0, v1, v2, v3;
                LDSM4(v0, v1, v2, v3,
                      vt_lane + (unsigned)(g*16*VH*2 + kc*32));
                MMAF16(o[2*g],   pa0, pa1, pa2, pa3, v0, v1);
                MMAF16(o[2*g+1], pa0, pa1, pa2, pa3, v2, v3);
            }
        }
    }

    // ---- normalize & write fp16 [B,S,H*HD] ----
    l0 += __shfl_xor_sync(0xffffffffu, l0, 1);
    l0 += __shfl_xor_sync(0xffffffffu, l0, 2);
    l1 += __shfl_xor_sync(0xffffffffu, l1, 1);
    l1 += __shfl_xor_sync(0xffffffffu, l1, 2);
    float inv0 = 1.f / l0, inv1 = 1.f / l1;

    const int b = bh >> 4, h = bh & 15;
    const int row0 = q0 + wid*16 + a_;
    __half* op0 = g_aoh + ((size_t)(b*S_ + row0))     * D_ + h*HD_;
    __half* op1 = g_aoh + ((size_t)(b*S_ + row0 + 8)) * D_ + h*HD_;
#pragma unroll
    for (int f = 0; f < 16; f++) {
        int c = f*8 + q_*2;
        *(unsigned*)(op0 + c) = h2pack(o[f][0]*inv0, o[f][1]*inv0);
        *(unsigned*)(op1 + c) = h2pack(o[f][2]*inv1, o[f][3]*inv1);
    }
}

// =====================================================================
extern "C" void kernel_launch(void* const* d_in, const int* in_sizes, int n_in,
                              void* d_out, int out_size)
{
    (void)in_sizes; (void)n_in; (void)out_size;
    const float* x    = (const float*)d_in[0];
    // d_in[1] = mask: exactly causal, implemented analytically
    const float* cosT = (const float*)d_in[2];
    const float* sinT = (const float*)d_in[3];
    const float* Wq   = (const float*)d_in[4];
    const float* Wk   = (const float*)d_in[5];
    const float* Wv   = (const float*)d_in[6];
    const float* Wo   = (const float*)d_in[7];
    float* out = (float*)d_out;

    cudaFuncSetAttribute(gemm_h,
        cudaFuncAttributeMaxDynamicSharedMemorySize, GS);
    cudaFuncSetAttribute(attn_h,
        cudaFuncAttributeMaxDynamicSharedMemorySize, ATT3_SMEM);

    // 0) fp32 -> fp16 conversion of inputs (dst chosen device-side)
    f2h_kernel<<<(B_*S_*D_)/2048, 256>>>(x,  0);
    f2h_kernel<<<(D_*D_)/2048, 256>>>(Wq, 1);
    f2h_kernel<<<(D_*D_)/2048, 256>>>(Wk, 2);
    f2h_kernel<<<(D_*D_)/2048, 256>>>(Wv, 3);
    f2h_kernel<<<(D_*D_)/2048, 256>>>(Wo, 4);

    // 1) fused QKV projection -> fp16 [B,H,S,HD]
    dim3 gqkv(D_/TN, M_/TM, 3);
    gemm_h<<<gqkv, 256, GS>>>(nullptr, 0);

    // 2) RoPE in place on q,k (fp16)
    rope_h<<<(B_*H_*S_*16)/256, 256>>>(cosT, sinT);

    // 3) causal flash attention -> fp16 g_aoh [B,S,D]
    dim3 gatt(S_/128, B_*H_);
    attn_h<<<gatt, 256, ATT3_SMEM>>>();

    // 4) output projection -> fp32 d_out
    dim3 go(D_/TN, M_/TM, 1);
    gemm_h<<<go, 256, GS>>>(out, 1);
}